// round 8
// baseline (speedup 1.0000x reference)
#include <cuda_runtime.h>
#include <cuda_bf16.h>
#include <math.h>
#include <stdint.h>

#define S_LEN  2048
#define HID    2048
#define NHEADS 16
#define HS     128
#define QKV_N  6144
#define KTOT   2048
#define INV_NORM 0.08838834764831845f

// ---------------- scratch (device globals; no allocations allowed) ----------
__device__ float g_V[(size_t)NHEADS * S_LEN * HS];        // fp32 V [h][s][d]
__device__ __nv_bfloat16 g_Ah[(size_t)S_LEN * HID];
__device__ __nv_bfloat16 g_Al[(size_t)S_LEN * HID];
__device__ __nv_bfloat16 g_Bqh[(size_t)QKV_N * HID];
__device__ __nv_bfloat16 g_Bql[(size_t)QKV_N * HID];
__device__ __nv_bfloat16 g_Boh[(size_t)HID * HID];
__device__ __nv_bfloat16 g_Bol[(size_t)HID * HID];
__device__ __nv_bfloat16 g_ATh[(size_t)S_LEN * HID];
__device__ __nv_bfloat16 g_ATl[(size_t)S_LEN * HID];
__device__ __nv_bfloat16 g_Qh[(size_t)NHEADS * S_LEN * HS];
__device__ __nv_bfloat16 g_Ql[(size_t)NHEADS * S_LEN * HS];
__device__ __nv_bfloat16 g_Kh[(size_t)NHEADS * S_LEN * HS];
__device__ __nv_bfloat16 g_Kl[(size_t)NHEADS * S_LEN * HS];
__device__ __nv_bfloat16 g_Vth[(size_t)NHEADS * HS * S_LEN];
__device__ __nv_bfloat16 g_Vtl[(size_t)NHEADS * HS * S_LEN];

// exact fp32 roundings of 10000^(-j/16) = 10^(-j/4)
__device__ __constant__ float c_invfreq[16] = {
    1.0f, 0.5623413251903491f, 0.31622776601683794f, 0.17782794100389228f,
    0.1f, 0.05623413251903491f, 0.03162277660168379f, 0.017782794100389228f,
    0.01f, 0.005623413251903491f, 0.0031622776601683794f, 0.0017782794100389228f,
    0.001f, 0.0005623413251903491f, 0.00031622776601683794f, 0.00017782794100389228f
};

// ------------------------------- helpers ------------------------------------
__device__ __forceinline__ uint32_t smem_to_u32(const void* p) {
    uint32_t a;
    asm("{ .reg .u64 t; cvta.to.shared.u64 t, %1; cvt.u32.u64 %0, t; }"
        : "=r"(a) : "l"(p));
    return a;
}
__device__ __forceinline__ void cp_async16(uint32_t dst, const void* src) {
    asm volatile("cp.async.cg.shared.global [%0], [%1], 16;"
                 :: "r"(dst), "l"(src) : "memory");
}
#define CP_COMMIT() asm volatile("cp.async.commit_group;" ::: "memory")
#define CP_WAIT(n)  asm volatile("cp.async.wait_group %0;" :: "n"(n) : "memory")

__device__ __forceinline__ void mma_bf16(float* c, const uint32_t* a, const uint32_t* b) {
    asm volatile(
        "mma.sync.aligned.m16n8k16.row.col.f32.bf16.bf16.f32 "
        "{%0,%1,%2,%3}, {%4,%5,%6,%7}, {%8,%9}, {%0,%1,%2,%3};"
        : "+f"(c[0]), "+f"(c[1]), "+f"(c[2]), "+f"(c[3])
        : "r"(a[0]), "r"(a[1]), "r"(a[2]), "r"(a[3]), "r"(b[0]), "r"(b[1]));
}
__device__ __forceinline__ void ldsm4(uint32_t& r0, uint32_t& r1, uint32_t& r2,
                                      uint32_t& r3, uint32_t addr) {
    asm volatile("ldmatrix.sync.aligned.m8n8.x4.shared.b16 {%0,%1,%2,%3}, [%4];"
        : "=r"(r0), "=r"(r1), "=r"(r2), "=r"(r3) : "r"(addr));
}
__device__ __forceinline__ uint32_t packbf(float lo, float hi) {
    uint32_t d;
    asm("cvt.rn.bf16x2.f32 %0, %1, %2;" : "=r"(d) : "f"(hi), "f"(lo));
    return d;
}
__device__ __forceinline__ uint32_t packbf_res(uint32_t hpack, float lo, float hi) {
    float rl = lo - __uint_as_float(hpack << 16);
    float rh = hi - __uint_as_float(hpack & 0xffff0000u);
    return packbf(rl, rh);
}

// ---------------------------------------------------------------------------
// Conversion kernels
// ---------------------------------------------------------------------------
__global__ __launch_bounds__(256) void conv_split(
    const float4* __restrict__ X, __nv_bfloat162* __restrict__ H,
    __nv_bfloat162* __restrict__ L)
{
    int i = blockIdx.x * 256 + threadIdx.x;
    float4 v = X[i];
    __nv_bfloat16 h0 = __float2bfloat16_rn(v.x), h1 = __float2bfloat16_rn(v.y);
    __nv_bfloat16 h2 = __float2bfloat16_rn(v.z), h3 = __float2bfloat16_rn(v.w);
    __nv_bfloat16 l0 = __float2bfloat16_rn(v.x - __bfloat162float(h0));
    __nv_bfloat16 l1 = __float2bfloat16_rn(v.y - __bfloat162float(h1));
    __nv_bfloat16 l2 = __float2bfloat16_rn(v.z - __bfloat162float(h2));
    __nv_bfloat16 l3 = __float2bfloat16_rn(v.w - __bfloat162float(h3));
    H[2 * i] = __halves2bfloat162(h0, h1); H[2 * i + 1] = __halves2bfloat162(h2, h3);
    L[2 * i] = __halves2bfloat162(l0, l1); L[2 * i + 1] = __halves2bfloat162(l2, l3);
}

__global__ __launch_bounds__(256) void conv_transpose_split(
    const float* __restrict__ B, __nv_bfloat16* __restrict__ H,
    __nv_bfloat16* __restrict__ L, int K, int N)
{
    __shared__ float t[32][33];
    int x = threadIdx.x & 31, y = threadIdx.x >> 5;
    int n0 = blockIdx.x * 32, k0 = blockIdx.y * 32;
#pragma unroll
    for (int j = 0; j < 32; j += 8)
        t[y + j][x] = B[(size_t)(k0 + y + j) * N + n0 + x];
    __syncthreads();
#pragma unroll
    for (int j = 0; j < 32; j += 8) {
        float v = t[x][y + j];
        __nv_bfloat16 h = __float2bfloat16_rn(v);
        __nv_bfloat16 l = __float2bfloat16_rn(v - __bfloat162float(h));
        size_t o = (size_t)(n0 + y + j) * K + k0 + x;
        H[o] = h; L[o] = l;
    }
}

__global__ __launch_bounds__(256) void vtrans()
{
    __shared__ float t[32][33];
    int x = threadIdx.x & 31, y = threadIdx.x >> 5;
    int s0 = blockIdx.x * 32, d0 = blockIdx.y * 32, h = blockIdx.z;
#pragma unroll
    for (int j = 0; j < 32; j += 8)
        t[y + j][x] = g_V[((size_t)h * S_LEN + s0 + y + j) * HS + d0 + x];
    __syncthreads();
#pragma unroll
    for (int j = 0; j < 32; j += 8) {
        float v = t[x][y + j];
        __nv_bfloat16 hv = __float2bfloat16_rn(v);
        size_t o = ((size_t)h * HS + d0 + y + j) * S_LEN + s0 + x;
        g_Vth[o] = hv;
        g_Vtl[o] = __float2bfloat16_rn(v - __bfloat162float(hv));
    }
}

// ---------------------------------------------------------------------------
// bf16x3 mma.sync GEMM. BM=64, BN=256, BK=32, 128 threads (4 warps, each
// 64x64 tile), 2-stage cp.async pipeline (sync before overwrite!), 2 CTAs/SM.
// ---------------------------------------------------------------------------
#define GBK 32
#define GNITER (KTOT / GBK)
#define ROWSTR 40
#define A_BUFH (64 * ROWSTR)       // 2560 halves
#define B_BUFH (256 * ROWSTR)      // 10240 halves
#define ST_AH 0
#define ST_AL A_BUFH
#define ST_BH (2 * A_BUFH)
#define ST_BL (2 * A_BUFH + B_BUFH)
#define STGH  (2 * A_BUFH + 2 * B_BUFH)   // 25600 halves = 51200 B
#define GSTAGES 2
#define GEMM_SMEM (GSTAGES * STGH * 2)    // 102400 B

__global__ __launch_bounds__(128, 2) void gemm_mma(
    const __nv_bfloat16* __restrict__ Ah, const __nv_bfloat16* __restrict__ Al,
    const __nv_bfloat16* __restrict__ Bh, const __nv_bfloat16* __restrict__ Bl,
    const float* __restrict__ bias, int N, float* __restrict__ Cout, int mode)
{
    extern __shared__ __align__(16) __nv_bfloat16 sm[];
    const int tid = threadIdx.x;
    const int wn = tid >> 5, lane = tid & 31;
    const int n0 = blockIdx.x * 256, m0 = blockIdx.y * 64;
    const uint32_t sbase = smem_to_u32(sm);

    const int r  = lane >> 2;
    const int c2 = (lane & 3) * 2;
    const int arow = ((lane >> 3) & 1) * 8 + (lane & 7);
    const int acol = (lane >> 4) * 8;
    const int brow = ((lane >> 4) & 1) * 8 + (lane & 7);
    const int bcol = ((lane >> 3) & 1) * 8;

    float acc[4][8][4];
#pragma unroll
    for (int i = 0; i < 4; i++)
#pragma unroll
        for (int j = 0; j < 8; j++)
#pragma unroll
            for (int q = 0; q < 4; q++) acc[i][j][q] = 0.f;

    auto load_stage = [&](int s, int k0) {
        const uint32_t st = sbase + (uint32_t)s * STGH * 2;
#pragma unroll
        for (int i = 0; i < 2; i++) {               // A: 256 chunks
            int c = tid + i * 128;
            int row = c >> 2, kc = c & 3;
            uint32_t doff = (uint32_t)(row * ROWSTR + kc * 8) * 2;
            size_t go = (size_t)(m0 + row) * KTOT + k0 + kc * 8;
            cp_async16(st + ST_AH * 2 + doff, Ah + go);
            cp_async16(st + ST_AL * 2 + doff, Al + go);
        }
#pragma unroll
        for (int i = 0; i < 8; i++) {               // B: 1024 chunks
            int c = tid + i * 128;
            int row = c >> 2, kc = c & 3;
            uint32_t doff = (uint32_t)(row * ROWSTR + kc * 8) * 2;
            size_t go = (size_t)(n0 + row) * KTOT + k0 + kc * 8;
            cp_async16(st + ST_BH * 2 + doff, Bh + go);
            cp_async16(st + ST_BL * 2 + doff, Bl + go);
        }
    };

    load_stage(0, 0); CP_COMMIT();
    load_stage(1, GBK); CP_COMMIT();

    for (int it = 0; it < GNITER; it++) {
        const int s = it & 1;
        if (it < GNITER - 1) { CP_WAIT(1); } else { CP_WAIT(0); }
        __syncthreads();

        const uint32_t stg = sbase + (uint32_t)s * STGH * 2;

#pragma unroll
        for (int ks = 0; ks < 2; ks++) {
            uint32_t ah[4][4], al[4][4], bh[8][2], bl[8][2];
#pragma unroll
            for (int i = 0; i < 4; i++) {
                uint32_t a = stg + (uint32_t)((i * 16 + arow) * ROWSTR
                                              + ks * 16 + acol) * 2;
                ldsm4(ah[i][0], ah[i][1], ah[i][2], ah[i][3], a + ST_AH * 2);
                ldsm4(al[i][0], al[i][1], al[i][2], al[i][3], a + ST_AL * 2);
            }
#pragma unroll
            for (int jp = 0; jp < 4; jp++) {
                uint32_t b = stg + (uint32_t)((wn * 64 + jp * 16 + brow) * ROWSTR
                                              + ks * 16 + bcol) * 2;
                ldsm4(bh[jp * 2][0], bh[jp * 2][1], bh[jp * 2 + 1][0], bh[jp * 2 + 1][1],
                      b + ST_BH * 2);
                ldsm4(bl[jp * 2][0], bl[jp * 2][1], bl[jp * 2 + 1][0], bl[jp * 2 + 1][1],
                      b + ST_BL * 2);
            }
#pragma unroll
            for (int i = 0; i < 4; i++)
#pragma unroll
                for (int j = 0; j < 8; j++) mma_bf16(acc[i][j], ah[i], bh[j]);
#pragma unroll
            for (int i = 0; i < 4; i++)
#pragma unroll
                for (int j = 0; j < 8; j++) mma_bf16(acc[i][j], ah[i], bl[j]);
#pragma unroll
            for (int i = 0; i < 4; i++)
#pragma unroll
                for (int j = 0; j < 8; j++) mma_bf16(acc[i][j], al[i], bh[j]);
        }
        if (it + 2 < GNITER) {
            // 2-stage: prefetch target aliases the stage just computed on.
            // Barrier ensures every warp is done reading before overwrite.
            __syncthreads();
            load_stage(s, (it + 2) * GBK);
            CP_COMMIT();
        }
    }

#pragma unroll
    for (int i = 0; i < 4; i++) {
#pragma unroll
        for (int j = 0; j < 8; j++) {
            int n = n0 + wn * 64 + j * 8 + c2;
            float2 bv = *reinterpret_cast<const float2*>(bias + n);
#pragma unroll
            for (int half = 0; half < 2; half++) {
                int m = m0 + i * 16 + r + half * 8;
                float2 v = make_float2(acc[i][j][half * 2] + bv.x,
                                       acc[i][j][half * 2 + 1] + bv.y);
                if (mode) {
                    *reinterpret_cast<float2*>(Cout + (size_t)m * N + n) = v;
                } else {
                    int h = n / 384, e = n - h * 384;
                    int seg = e >> 7, d = e & 127;
                    if (seg == 2) {
                        *reinterpret_cast<float2*>(g_V + ((size_t)h * S_LEN + m) * HS + d) = v;
                    } else {
                        if (d < 32) {   // fused rotary: partner is acc[i][j±2]
                            bool low = d < 16;
                            int jp = low ? j + 2 : j - 2;
                            int np = low ? n + 16 : n - 16;
                            float2 bvp = *reinterpret_cast<const float2*>(bias + np);
                            float px = acc[i][jp][half * 2] + bvp.x;
                            float py = acc[i][jp][half * 2 + 1] + bvp.y;
                            float f0 = (float)m * c_invfreq[d & 15];
                            float f1 = (float)m * c_invfreq[(d + 1) & 15];
                            float s0, c0, s1, c1;
                            sincosf(f0, &s0, &c0);
                            sincosf(f1, &s1, &c1);
                            if (low) { v.x = v.x * c0 - px * s0; v.y = v.y * c1 - py * s1; }
                            else     { v.x = v.x * c0 + px * s0; v.y = v.y * c1 + py * s1; }
                        }
                        uint32_t hp = packbf(v.x, v.y);
                        uint32_t lp = packbf_res(hp, v.x, v.y);
                        size_t off = ((size_t)h * S_LEN + m) * HS + d;
                        if (seg == 0) {
                            *reinterpret_cast<uint32_t*>(g_Qh + off) = hp;
                            *reinterpret_cast<uint32_t*>(g_Ql + off) = lp;
                        } else {
                            *reinterpret_cast<uint32_t*>(g_Kh + off) = hp;
                            *reinterpret_cast<uint32_t*>(g_Kl + off) = lp;
                        }
                    }
                }
            }
        }
    }
}

// ---------------------------------------------------------------------------
// Flash attention, mma.sync bf16x3 with ldmatrix fragment loads.
// ---------------------------------------------------------------------------
#define KSTR 136
#define VSTR 72
#define FSM_KH 0
#define FSM_KL (64 * KSTR)
#define FSM_VH (2 * 64 * KSTR)
#define FSM_VL (2 * 64 * KSTR + 128 * VSTR)
#define FLASH_SMEM ((2 * 64 * KSTR + 2 * 128 * VSTR) * 2)

__global__ __launch_bounds__(128) void flash_mma()
{
    const int h  = blockIdx.y;
    const int qt = (gridDim.x - 1) - blockIdx.x;
    const int q0 = qt * 64;

    extern __shared__ __align__(16) __nv_bfloat16 fsm[];
    const uint32_t sbase = smem_to_u32(fsm);

    const int tid = threadIdx.x;
    const int w = tid >> 5, lane = tid & 31;
    const int r = lane >> 2, c2 = (lane & 3) * 2;
    const int brow = ((lane >> 4) & 1) * 8 + (lane & 7);
    const int bcol = ((lane >> 3) & 1) * 8;
    const int qrow = q0 + w * 16 + r;

    const __nv_bfloat16* Qhg = g_Qh + (size_t)h * S_LEN * HS;
    const __nv_bfloat16* Qlg = g_Ql + (size_t)h * S_LEN * HS;
    const __nv_bfloat16* Khg = g_Kh + (size_t)h * S_LEN * HS;
    const __nv_bfloat16* Klg = g_Kl + (size_t)h * S_LEN * HS;
    const __nv_bfloat16* Vhg = g_Vth + (size_t)h * HS * S_LEN;
    const __nv_bfloat16* Vlg = g_Vtl + (size_t)h * HS * S_LEN;

    uint32_t qh[8][4], ql[8][4];
#pragma unroll
    for (int kc = 0; kc < 8; kc++) {
        size_t o0 = (size_t)qrow * HS + kc * 16 + c2;
        size_t o1 = (size_t)(qrow + 8) * HS + kc * 16 + c2;
        qh[kc][0] = *reinterpret_cast<const uint32_t*>(Qhg + o0);
        qh[kc][1] = *reinterpret_cast<const uint32_t*>(Qhg + o1);
        qh[kc][2] = *reinterpret_cast<const uint32_t*>(Qhg + o0 + 8);
        qh[kc][3] = *reinterpret_cast<const uint32_t*>(Qhg + o1 + 8);
        ql[kc][0] = *reinterpret_cast<const uint32_t*>(Qlg + o0);
        ql[kc][1] = *reinterpret_cast<const uint32_t*>(Qlg + o1);
        ql[kc][2] = *reinterpret_cast<const uint32_t*>(Qlg + o0 + 8);
        ql[kc][3] = *reinterpret_cast<const uint32_t*>(Qlg + o1 + 8);
    }

    float o[16][4];
#pragma unroll
    for (int t = 0; t < 16; t++)
#pragma unroll
        for (int q = 0; q < 4; q++) o[t][q] = 0.f;
    float m2[2] = {-1e30f, -1e30f};
    float l[2] = {0.f, 0.f};

    const float SC = INV_NORM * 1.4426950408889634f;

    for (int kt = 0; kt <= qt; kt++) {
        const int kb0 = kt * 64;
        __syncthreads();
#pragma unroll
        for (int i = 0; i < 8; i++) {
            int c = i * 128 + tid;
            int rowk = c >> 4, colk = c & 15;
            uint32_t dK = (uint32_t)(rowk * KSTR + colk * 8) * 2;
            size_t gK = (size_t)(kb0 + rowk) * HS + colk * 8;
            cp_async16(sbase + FSM_KH * 2 + dK, Khg + gK);
            cp_async16(sbase + FSM_KL * 2 + dK, Klg + gK);
            int rowd = c >> 3, cols = c & 7;
            uint32_t dV = (uint32_t)(rowd * VSTR + cols * 8) * 2;
            size_t gV = (size_t)rowd * S_LEN + kb0 + cols * 8;
            cp_async16(sbase + FSM_VH * 2 + dV, Vhg + gV);
            cp_async16(sbase + FSM_VL * 2 + dV, Vlg + gV);
        }
        CP_COMMIT(); CP_WAIT(0);
        __syncthreads();

        float sacc[8][4];
#pragma unroll
        for (int j = 0; j < 8; j++)
#pragma unroll
            for (int q = 0; q < 4; q++) sacc[j][q] = 0.f;
#pragma unroll
        for (int kc = 0; kc < 8; kc++) {
#pragma unroll
            for (int jh = 0; jh < 2; jh++) {
                uint32_t bh[4][2], bl[4][2];
#pragma unroll
                for (int jp = 0; jp < 2; jp++) {
                    uint32_t a = sbase
                        + (uint32_t)(((jh * 4 + jp * 2) * 8 + brow) * KSTR
                                     + kc * 16 + bcol) * 2;
                    ldsm4(bh[jp * 2][0], bh[jp * 2][1],
                          bh[jp * 2 + 1][0], bh[jp * 2 + 1][1], a);
                    ldsm4(bl[jp * 2][0], bl[jp * 2][1],
                          bl[jp * 2 + 1][0], bl[jp * 2 + 1][1], a + FSM_KL * 2);
                }
#pragma unroll
                for (int jj = 0; jj < 4; jj++) mma_bf16(sacc[jh * 4 + jj], qh[kc], bh[jj]);
#pragma unroll
                for (int jj = 0; jj < 4; jj++) mma_bf16(sacc[jh * 4 + jj], qh[kc], bl[jj]);
#pragma unroll
                for (int jj = 0; jj < 4; jj++) mma_bf16(sacc[jh * 4 + jj], ql[kc], bh[jj]);
            }
        }

        if (kt == qt) {
#pragma unroll
            for (int j = 0; j < 8; j++) {
#pragma unroll
                for (int q = 0; q < 4; q++) {
                    int col = kb0 + j * 8 + c2 + (q & 1);
                    int row = qrow + ((q >= 2) ? 8 : 0);
                    if (col > row) sacc[j][q] = -1e30f;
                }
            }
        }

#pragma unroll
        for (int g = 0; g < 2; g++) {
            float rm = -1e30f;
#pragma unroll
            for (int j = 0; j < 8; j++)
                rm = fmaxf(rm, fmaxf(sacc[j][2 * g], sacc[j][2 * g + 1]));
            rm *= SC;
            rm = fmaxf(rm, __shfl_xor_sync(0xffffffffu, rm, 1));
            rm = fmaxf(rm, __shfl_xor_sync(0xffffffffu, rm, 2));
            float mn = fmaxf(m2[g], rm);
            float alpha = exp2f(m2[g] - mn);
            m2[g] = mn;
            float rs = 0.f;
#pragma unroll
            for (int j = 0; j < 8; j++) {
#pragma unroll
                for (int q = 2 * g; q < 2 * g + 2; q++) {
                    float p = exp2f(sacc[j][q] * SC - mn);
                    sacc[j][q] = p;
                    rs += p;
                }
            }
            rs += __shfl_xor_sync(0xffffffffu, rs, 1);
            rs += __shfl_xor_sync(0xffffffffu, rs, 2);
            l[g] = l[g] * alpha + rs;
#pragma unroll
            for (int t = 0; t < 16; t++) {
                o[t][2 * g]     *= alpha;
                o[t][2 * g + 1] *= alpha;
            }
        }

#pragma unroll
        for (int kc2 = 0; kc2 < 4; kc2++) {
            uint32_t ph[4], pl[4];
            ph[0] = packbf(sacc[2 * kc2][0], sacc[2 * kc2][1]);
            ph[1] = packbf(sacc[2 * kc2][2], sacc[2 * kc2][3]);
            ph[2] = packbf(sacc[2 * kc2 + 1][0], sacc[2 * kc2 + 1][1]);
            ph[3] = packbf(sacc[2 * kc2 + 1][2], sacc[2 * kc2 + 1][3]);
            pl[0] = packbf_res(ph[0], sacc[2 * kc2][0], sacc[2 * kc2][1]);
            pl[1] = packbf_res(ph[1], sacc[2 * kc2][2], sacc[2 * kc2][3]);
            pl[2] = packbf_res(ph[2], sacc[2 * kc2 + 1][0], sacc[2 * kc2 + 1][1]);
            pl[3] = packbf_res(ph[3], sacc[2 * kc2 + 1][2], sacc[2 * kc2 + 1][3]);
#pragma unroll
            for (int jg = 0; jg < 4; jg++) {
                uint32_t vh[4][2], vl[4][2];
#pragma unroll
                for (int jp = 0; jp < 2; jp++) {
                    uint32_t a = sbase + FSM_VH * 2
                        + (uint32_t)(((jg * 4 + jp * 2) * 8 + brow) * VSTR
                                     + kc2 * 16 + bcol) * 2;
                    ldsm4(vh[jp * 2][0], vh[jp * 2][1],
                          vh[jp * 2 + 1][0], vh[jp * 2 + 1][1], a);
                    ldsm4(vl[jp * 2][0], vl[jp * 2][1],
                          vl[jp * 2 + 1][0], vl[jp * 2 + 1][1],
                          a + (FSM_VL - FSM_VH) * 2);
                }
#pragma unroll
                for (int jj = 0; jj < 4; jj++) mma_bf16(o[jg * 4 + jj], ph, vh[jj]);
#pragma unroll
                for (int jj = 0; jj < 4; jj++) mma_bf16(o[jg * 4 + jj], ph, vl[jj]);
#pragma unroll
                for (int jj = 0; jj < 4; jj++) mma_bf16(o[jg * 4 + jj], pl, vh[jj]);
            }
        }
    }

    float inv0 = 1.f / l[0], inv1 = 1.f / l[1];
#pragma unroll
    for (int jd = 0; jd < 16; jd++) {
        int col = h * HS + jd * 8 + c2;
        {
            float v0 = o[jd][0] * inv0, v1 = o[jd][1] * inv0;
            uint32_t hp = packbf(v0, v1);
            uint32_t lp = packbf_res(hp, v0, v1);
            *reinterpret_cast<uint32_t*>(g_ATh + (size_t)qrow * HID + col) = hp;
            *reinterpret_cast<uint32_t*>(g_ATl + (size_t)qrow * HID + col) = lp;
        }
        {
            float v0 = o[jd][2] * inv1, v1 = o[jd][3] * inv1;
            uint32_t hp = packbf(v0, v1);
            uint32_t lp = packbf_res(hp, v0, v1);
            *reinterpret_cast<uint32_t*>(g_ATh + (size_t)(qrow + 8) * HID + col) = hp;
            *reinterpret_cast<uint32_t*>(g_ATl + (size_t)(qrow + 8) * HID + col) = lp;
        }
    }
}

// ---------------------------------------------------------------------------
extern "C" void kernel_launch(void* const* d_in, const int* in_sizes, int n_in,
                              void* d_out, int out_size)
{
    (void)in_sizes; (void)n_in; (void)out_size;
    const float* hidden = (const float*)d_in[0];
    const float* qkvk = (const float*)d_in[2];
    const float* qkvb = (const float*)d_in[3];
    const float* outk = (const float*)d_in[4];
    const float* outb = (const float*)d_in[5];
    float* out = (float*)d_out;

    cudaFuncSetAttribute(gemm_mma, cudaFuncAttributeMaxDynamicSharedMemorySize, GEMM_SMEM);
    cudaFuncSetAttribute(flash_mma, cudaFuncAttributeMaxDynamicSharedMemorySize, FLASH_SMEM);

    void *Ah, *Al, *Bqh, *Bql, *Boh, *Bol, *ATh, *ATl;
    cudaGetSymbolAddress(&Ah, g_Ah);   cudaGetSymbolAddress(&Al, g_Al);
    cudaGetSymbolAddress(&Bqh, g_Bqh); cudaGetSymbolAddress(&Bql, g_Bql);
    cudaGetSymbolAddress(&Boh, g_Boh); cudaGetSymbolAddress(&Bol, g_Bol);
    cudaGetSymbolAddress(&ATh, g_ATh); cudaGetSymbolAddress(&ATl, g_ATl);

    conv_split<<<(S_LEN * HID) / 1024, 256>>>(
        (const float4*)hidden, (__nv_bfloat162*)Ah, (__nv_bfloat162*)Al);
    conv_transpose_split<<<dim3(QKV_N / 32, HID / 32), 256>>>(
        qkvk, (__nv_bfloat16*)Bqh, (__nv_bfloat16*)Bql, HID, QKV_N);
    conv_transpose_split<<<dim3(HID / 32, HID / 32), 256>>>(
        outk, (__nv_bfloat16*)Boh, (__nv_bfloat16*)Bol, HID, HID);

    // QKV projection + fused rotary + Q/K split (V -> fp32)
    gemm_mma<<<dim3(QKV_N / 256, S_LEN / 64), 128, GEMM_SMEM>>>(
        (const __nv_bfloat16*)Ah, (const __nv_bfloat16*)Al,
        (const __nv_bfloat16*)Bqh, (const __nv_bfloat16*)Bql,
        qkvb, QKV_N, nullptr, 0);

    vtrans<<<dim3(S_LEN / 32, HS / 32, NHEADS), 256>>>();

    flash_mma<<<dim3(S_LEN / 64, NHEADS), 128, FLASH_SMEM>>>();

    gemm_mma<<<dim3(HID / 256, S_LEN / 64), 128, GEMM_SMEM>>>(
        (const __nv_bfloat16*)ATh, (const __nv_bfloat16*)ATl,
        (const __nv_bfloat16*)Boh, (const __nv_bfloat16*)Bol,
        outb, HID, out, 1);
}

// round 9
// speedup vs baseline: 1.0197x; 1.0197x over previous
#include <cuda_runtime.h>
#include <cuda_bf16.h>
#include <math.h>
#include <stdint.h>

#define S_LEN  2048
#define HID    2048
#define NHEADS 16
#define HS     128
#define QKV_N  6144
#define KTOT   2048
#define INV_NORM 0.08838834764831845f

// ---------------- scratch (device globals; no allocations allowed) ----------
__device__ float g_V[(size_t)NHEADS * S_LEN * HS];        // fp32 V [h][s][d]
__device__ __nv_bfloat16 g_Ah[(size_t)S_LEN * HID];
__device__ __nv_bfloat16 g_Al[(size_t)S_LEN * HID];
__device__ __nv_bfloat16 g_Bqh[(size_t)QKV_N * HID];
__device__ __nv_bfloat16 g_Bql[(size_t)QKV_N * HID];
__device__ __nv_bfloat16 g_Boh[(size_t)HID * HID];
__device__ __nv_bfloat16 g_Bol[(size_t)HID * HID];
__device__ __nv_bfloat16 g_ATh[(size_t)S_LEN * HID];
__device__ __nv_bfloat16 g_ATl[(size_t)S_LEN * HID];
__device__ __nv_bfloat16 g_Qh[(size_t)NHEADS * S_LEN * HS];
__device__ __nv_bfloat16 g_Ql[(size_t)NHEADS * S_LEN * HS];
__device__ __nv_bfloat16 g_Kh[(size_t)NHEADS * S_LEN * HS];
__device__ __nv_bfloat16 g_Kl[(size_t)NHEADS * S_LEN * HS];
__device__ __nv_bfloat16 g_Vth[(size_t)NHEADS * HS * S_LEN];
__device__ __nv_bfloat16 g_Vtl[(size_t)NHEADS * HS * S_LEN];

// exact fp32 roundings of 10000^(-j/16) = 10^(-j/4)
__device__ __constant__ float c_invfreq[16] = {
    1.0f, 0.5623413251903491f, 0.31622776601683794f, 0.17782794100389228f,
    0.1f, 0.05623413251903491f, 0.03162277660168379f, 0.017782794100389228f,
    0.01f, 0.005623413251903491f, 0.0031622776601683794f, 0.0017782794100389228f,
    0.001f, 0.0005623413251903491f, 0.00031622776601683794f, 0.00017782794100389228f
};

// ------------------------------- helpers ------------------------------------
__device__ __forceinline__ uint32_t smem_to_u32(const void* p) {
    uint32_t a;
    asm("{ .reg .u64 t; cvta.to.shared.u64 t, %1; cvt.u32.u64 %0, t; }"
        : "=r"(a) : "l"(p));
    return a;
}
__device__ __forceinline__ void cp_async16(uint32_t dst, const void* src) {
    asm volatile("cp.async.cg.shared.global [%0], [%1], 16;"
                 :: "r"(dst), "l"(src) : "memory");
}
#define CP_COMMIT() asm volatile("cp.async.commit_group;" ::: "memory")
#define CP_WAIT(n)  asm volatile("cp.async.wait_group %0;" :: "n"(n) : "memory")

__device__ __forceinline__ void mma_bf16(float* c, const uint32_t* a, const uint32_t* b) {
    asm volatile(
        "mma.sync.aligned.m16n8k16.row.col.f32.bf16.bf16.f32 "
        "{%0,%1,%2,%3}, {%4,%5,%6,%7}, {%8,%9}, {%0,%1,%2,%3};"
        : "+f"(c[0]), "+f"(c[1]), "+f"(c[2]), "+f"(c[3])
        : "r"(a[0]), "r"(a[1]), "r"(a[2]), "r"(a[3]), "r"(b[0]), "r"(b[1]));
}
__device__ __forceinline__ void ldsm4(uint32_t& r0, uint32_t& r1, uint32_t& r2,
                                      uint32_t& r3, uint32_t addr) {
    asm volatile("ldmatrix.sync.aligned.m8n8.x4.shared.b16 {%0,%1,%2,%3}, [%4];"
        : "=r"(r0), "=r"(r1), "=r"(r2), "=r"(r3) : "r"(addr));
}
__device__ __forceinline__ uint32_t packbf(float lo, float hi) {
    uint32_t d;
    asm("cvt.rn.bf16x2.f32 %0, %1, %2;" : "=r"(d) : "f"(hi), "f"(lo));
    return d;
}
__device__ __forceinline__ uint32_t packbf_res(uint32_t hpack, float lo, float hi) {
    float rl = lo - __uint_as_float(hpack << 16);
    float rh = hi - __uint_as_float(hpack & 0xffff0000u);
    return packbf(rl, rh);
}

// ---------------------------------------------------------------------------
// Conversion kernels
// ---------------------------------------------------------------------------
__global__ __launch_bounds__(256) void conv_split(
    const float4* __restrict__ X, __nv_bfloat162* __restrict__ H,
    __nv_bfloat162* __restrict__ L)
{
    int i = blockIdx.x * 256 + threadIdx.x;
    float4 v = X[i];
    __nv_bfloat16 h0 = __float2bfloat16_rn(v.x), h1 = __float2bfloat16_rn(v.y);
    __nv_bfloat16 h2 = __float2bfloat16_rn(v.z), h3 = __float2bfloat16_rn(v.w);
    __nv_bfloat16 l0 = __float2bfloat16_rn(v.x - __bfloat162float(h0));
    __nv_bfloat16 l1 = __float2bfloat16_rn(v.y - __bfloat162float(h1));
    __nv_bfloat16 l2 = __float2bfloat16_rn(v.z - __bfloat162float(h2));
    __nv_bfloat16 l3 = __float2bfloat16_rn(v.w - __bfloat162float(h3));
    H[2 * i] = __halves2bfloat162(h0, h1); H[2 * i + 1] = __halves2bfloat162(h2, h3);
    L[2 * i] = __halves2bfloat162(l0, l1); L[2 * i + 1] = __halves2bfloat162(l2, l3);
}

__global__ __launch_bounds__(256) void conv_transpose_split(
    const float* __restrict__ B, __nv_bfloat16* __restrict__ H,
    __nv_bfloat16* __restrict__ L, int K, int N)
{
    __shared__ float t[32][33];
    int x = threadIdx.x & 31, y = threadIdx.x >> 5;
    int n0 = blockIdx.x * 32, k0 = blockIdx.y * 32;
#pragma unroll
    for (int j = 0; j < 32; j += 8)
        t[y + j][x] = B[(size_t)(k0 + y + j) * N + n0 + x];
    __syncthreads();
#pragma unroll
    for (int j = 0; j < 32; j += 8) {
        float v = t[x][y + j];
        __nv_bfloat16 h = __float2bfloat16_rn(v);
        __nv_bfloat16 l = __float2bfloat16_rn(v - __bfloat162float(h));
        size_t o = (size_t)(n0 + y + j) * K + k0 + x;
        H[o] = h; L[o] = l;
    }
}

__global__ __launch_bounds__(256) void vtrans()
{
    __shared__ float t[32][33];
    int x = threadIdx.x & 31, y = threadIdx.x >> 5;
    int s0 = blockIdx.x * 32, d0 = blockIdx.y * 32, h = blockIdx.z;
#pragma unroll
    for (int j = 0; j < 32; j += 8)
        t[y + j][x] = g_V[((size_t)h * S_LEN + s0 + y + j) * HS + d0 + x];
    __syncthreads();
#pragma unroll
    for (int j = 0; j < 32; j += 8) {
        float v = t[x][y + j];
        __nv_bfloat16 hv = __float2bfloat16_rn(v);
        size_t o = ((size_t)h * HS + d0 + y + j) * S_LEN + s0 + x;
        g_Vth[o] = hv;
        g_Vtl[o] = __float2bfloat16_rn(v - __bfloat162float(hv));
    }
}

// ---------------------------------------------------------------------------
// bf16x3 mma.sync GEMM. BM=64, BN=128, BK=32, 128 threads (4 warps, each
// 64x32 tile), 2-stage cp.async pipeline with sync-before-overwrite,
// 3 CTAs/SM for cross-CTA bubble filling.
// ---------------------------------------------------------------------------
#define GBK 32
#define GNITER (KTOT / GBK)
#define ROWSTR 40
#define A_BUFH (64 * ROWSTR)       // 2560 halves
#define B_BUFH (128 * ROWSTR)      // 5120 halves
#define ST_AH 0
#define ST_AL A_BUFH
#define ST_BH (2 * A_BUFH)
#define ST_BL (2 * A_BUFH + B_BUFH)
#define STGH  (2 * A_BUFH + 2 * B_BUFH)   // 15360 halves = 30720 B
#define GSTAGES 2
#define GEMM_SMEM (GSTAGES * STGH * 2)    // 61440 B -> 3 CTAs/SM

__global__ __launch_bounds__(128, 3) void gemm_mma(
    const __nv_bfloat16* __restrict__ Ah, const __nv_bfloat16* __restrict__ Al,
    const __nv_bfloat16* __restrict__ Bh, const __nv_bfloat16* __restrict__ Bl,
    const float* __restrict__ bias, int N, float* __restrict__ Cout, int mode)
{
    extern __shared__ __align__(16) __nv_bfloat16 sm[];
    const int tid = threadIdx.x;
    const int wn = tid >> 5, lane = tid & 31;
    const int n0 = blockIdx.x * 128, m0 = blockIdx.y * 64;
    const uint32_t sbase = smem_to_u32(sm);

    const int r  = lane >> 2;
    const int c2 = (lane & 3) * 2;
    const int arow = ((lane >> 3) & 1) * 8 + (lane & 7);
    const int acol = (lane >> 4) * 8;
    const int brow = ((lane >> 4) & 1) * 8 + (lane & 7);
    const int bcol = ((lane >> 3) & 1) * 8;

    float acc[4][4][4];
#pragma unroll
    for (int i = 0; i < 4; i++)
#pragma unroll
        for (int j = 0; j < 4; j++)
#pragma unroll
            for (int q = 0; q < 4; q++) acc[i][j][q] = 0.f;

    auto load_stage = [&](int s, int k0) {
        const uint32_t st = sbase + (uint32_t)s * STGH * 2;
#pragma unroll
        for (int i = 0; i < 2; i++) {               // A: 256 chunks
            int c = tid + i * 128;
            int row = c >> 2, kc = c & 3;
            uint32_t doff = (uint32_t)(row * ROWSTR + kc * 8) * 2;
            size_t go = (size_t)(m0 + row) * KTOT + k0 + kc * 8;
            cp_async16(st + ST_AH * 2 + doff, Ah + go);
            cp_async16(st + ST_AL * 2 + doff, Al + go);
        }
#pragma unroll
        for (int i = 0; i < 4; i++) {               // B: 512 chunks
            int c = tid + i * 128;
            int row = c >> 2, kc = c & 3;
            uint32_t doff = (uint32_t)(row * ROWSTR + kc * 8) * 2;
            size_t go = (size_t)(n0 + row) * KTOT + k0 + kc * 8;
            cp_async16(st + ST_BH * 2 + doff, Bh + go);
            cp_async16(st + ST_BL * 2 + doff, Bl + go);
        }
    };

    load_stage(0, 0); CP_COMMIT();
    load_stage(1, GBK); CP_COMMIT();

    for (int it = 0; it < GNITER; it++) {
        const int s = it & 1;
        if (it < GNITER - 1) { CP_WAIT(1); } else { CP_WAIT(0); }
        __syncthreads();

        const uint32_t stg = sbase + (uint32_t)s * STGH * 2;

#pragma unroll
        for (int ks = 0; ks < 2; ks++) {
            uint32_t ah[4][4], al[4][4], bh[4][2], bl[4][2];
#pragma unroll
            for (int i = 0; i < 4; i++) {
                uint32_t a = stg + (uint32_t)((i * 16 + arow) * ROWSTR
                                              + ks * 16 + acol) * 2;
                ldsm4(ah[i][0], ah[i][1], ah[i][2], ah[i][3], a + ST_AH * 2);
                ldsm4(al[i][0], al[i][1], al[i][2], al[i][3], a + ST_AL * 2);
            }
#pragma unroll
            for (int jp = 0; jp < 2; jp++) {
                uint32_t b = stg + (uint32_t)((wn * 32 + jp * 16 + brow) * ROWSTR
                                              + ks * 16 + bcol) * 2;
                ldsm4(bh[jp * 2][0], bh[jp * 2][1], bh[jp * 2 + 1][0], bh[jp * 2 + 1][1],
                      b + ST_BH * 2);
                ldsm4(bl[jp * 2][0], bl[jp * 2][1], bl[jp * 2 + 1][0], bl[jp * 2 + 1][1],
                      b + ST_BL * 2);
            }
#pragma unroll
            for (int i = 0; i < 4; i++)
#pragma unroll
                for (int j = 0; j < 4; j++) mma_bf16(acc[i][j], ah[i], bh[j]);
#pragma unroll
            for (int i = 0; i < 4; i++)
#pragma unroll
                for (int j = 0; j < 4; j++) mma_bf16(acc[i][j], ah[i], bl[j]);
#pragma unroll
            for (int i = 0; i < 4; i++)
#pragma unroll
                for (int j = 0; j < 4; j++) mma_bf16(acc[i][j], al[i], bh[j]);
        }
        if (it + 2 < GNITER) {
            // 2-stage: prefetch target aliases the stage just computed on.
            // Barrier ensures every warp is done reading before overwrite.
            __syncthreads();
            load_stage(s, (it + 2) * GBK);
            CP_COMMIT();
        }
    }

#pragma unroll
    for (int i = 0; i < 4; i++) {
#pragma unroll
        for (int j = 0; j < 4; j++) {
            int n = n0 + wn * 32 + j * 8 + c2;
            float2 bv = *reinterpret_cast<const float2*>(bias + n);
#pragma unroll
            for (int half = 0; half < 2; half++) {
                int m = m0 + i * 16 + r + half * 8;
                float2 v = make_float2(acc[i][j][half * 2] + bv.x,
                                       acc[i][j][half * 2 + 1] + bv.y);
                if (mode) {
                    *reinterpret_cast<float2*>(Cout + (size_t)m * N + n) = v;
                } else {
                    int h = n / 384, e = n - h * 384;
                    int seg = e >> 7, d = e & 127;
                    if (seg == 2) {
                        *reinterpret_cast<float2*>(g_V + ((size_t)h * S_LEN + m) * HS + d) = v;
                    } else {
                        if (d < 32) {   // fused rotary: partner is acc[i][j±2]
                            bool low = d < 16;
                            int jp = low ? j + 2 : j - 2;
                            int np = low ? n + 16 : n - 16;
                            float2 bvp = *reinterpret_cast<const float2*>(bias + np);
                            float px = acc[i][jp][half * 2] + bvp.x;
                            float py = acc[i][jp][half * 2 + 1] + bvp.y;
                            float f0 = (float)m * c_invfreq[d & 15];
                            float f1 = (float)m * c_invfreq[(d + 1) & 15];
                            float s0, c0, s1, c1;
                            sincosf(f0, &s0, &c0);
                            sincosf(f1, &s1, &c1);
                            if (low) { v.x = v.x * c0 - px * s0; v.y = v.y * c1 - py * s1; }
                            else     { v.x = v.x * c0 + px * s0; v.y = v.y * c1 + py * s1; }
                        }
                        uint32_t hp = packbf(v.x, v.y);
                        uint32_t lp = packbf_res(hp, v.x, v.y);
                        size_t off = ((size_t)h * S_LEN + m) * HS + d;
                        if (seg == 0) {
                            *reinterpret_cast<uint32_t*>(g_Qh + off) = hp;
                            *reinterpret_cast<uint32_t*>(g_Ql + off) = lp;
                        } else {
                            *reinterpret_cast<uint32_t*>(g_Kh + off) = hp;
                            *reinterpret_cast<uint32_t*>(g_Kl + off) = lp;
                        }
                    }
                }
            }
        }
    }
}

// ---------------------------------------------------------------------------
// Flash attention, mma.sync bf16x3 with ldmatrix fragment loads.
// ---------------------------------------------------------------------------
#define KSTR 136
#define VSTR 72
#define FSM_KH 0
#define FSM_KL (64 * KSTR)
#define FSM_VH (2 * 64 * KSTR)
#define FSM_VL (2 * 64 * KSTR + 128 * VSTR)
#define FLASH_SMEM ((2 * 64 * KSTR + 2 * 128 * VSTR) * 2)

__global__ __launch_bounds__(128) void flash_mma()
{
    const int h  = blockIdx.y;
    const int qt = (gridDim.x - 1) - blockIdx.x;
    const int q0 = qt * 64;

    extern __shared__ __align__(16) __nv_bfloat16 fsm[];
    const uint32_t sbase = smem_to_u32(fsm);

    const int tid = threadIdx.x;
    const int w = tid >> 5, lane = tid & 31;
    const int r = lane >> 2, c2 = (lane & 3) * 2;
    const int brow = ((lane >> 4) & 1) * 8 + (lane & 7);
    const int bcol = ((lane >> 3) & 1) * 8;
    const int qrow = q0 + w * 16 + r;

    const __nv_bfloat16* Qhg = g_Qh + (size_t)h * S_LEN * HS;
    const __nv_bfloat16* Qlg = g_Ql + (size_t)h * S_LEN * HS;
    const __nv_bfloat16* Khg = g_Kh + (size_t)h * S_LEN * HS;
    const __nv_bfloat16* Klg = g_Kl + (size_t)h * S_LEN * HS;
    const __nv_bfloat16* Vhg = g_Vth + (size_t)h * HS * S_LEN;
    const __nv_bfloat16* Vlg = g_Vtl + (size_t)h * HS * S_LEN;

    uint32_t qh[8][4], ql[8][4];
#pragma unroll
    for (int kc = 0; kc < 8; kc++) {
        size_t o0 = (size_t)qrow * HS + kc * 16 + c2;
        size_t o1 = (size_t)(qrow + 8) * HS + kc * 16 + c2;
        qh[kc][0] = *reinterpret_cast<const uint32_t*>(Qhg + o0);
        qh[kc][1] = *reinterpret_cast<const uint32_t*>(Qhg + o1);
        qh[kc][2] = *reinterpret_cast<const uint32_t*>(Qhg + o0 + 8);
        qh[kc][3] = *reinterpret_cast<const uint32_t*>(Qhg + o1 + 8);
        ql[kc][0] = *reinterpret_cast<const uint32_t*>(Qlg + o0);
        ql[kc][1] = *reinterpret_cast<const uint32_t*>(Qlg + o1);
        ql[kc][2] = *reinterpret_cast<const uint32_t*>(Qlg + o0 + 8);
        ql[kc][3] = *reinterpret_cast<const uint32_t*>(Qlg + o1 + 8);
    }

    float o[16][4];
#pragma unroll
    for (int t = 0; t < 16; t++)
#pragma unroll
        for (int q = 0; q < 4; q++) o[t][q] = 0.f;
    float m2[2] = {-1e30f, -1e30f};
    float l[2] = {0.f, 0.f};

    const float SC = INV_NORM * 1.4426950408889634f;

    for (int kt = 0; kt <= qt; kt++) {
        const int kb0 = kt * 64;
        __syncthreads();
#pragma unroll
        for (int i = 0; i < 8; i++) {
            int c = i * 128 + tid;
            int rowk = c >> 4, colk = c & 15;
            uint32_t dK = (uint32_t)(rowk * KSTR + colk * 8) * 2;
            size_t gK = (size_t)(kb0 + rowk) * HS + colk * 8;
            cp_async16(sbase + FSM_KH * 2 + dK, Khg + gK);
            cp_async16(sbase + FSM_KL * 2 + dK, Klg + gK);
            int rowd = c >> 3, cols = c & 7;
            uint32_t dV = (uint32_t)(rowd * VSTR + cols * 8) * 2;
            size_t gV = (size_t)rowd * S_LEN + kb0 + cols * 8;
            cp_async16(sbase + FSM_VH * 2 + dV, Vhg + gV);
            cp_async16(sbase + FSM_VL * 2 + dV, Vlg + gV);
        }
        CP_COMMIT(); CP_WAIT(0);
        __syncthreads();

        float sacc[8][4];
#pragma unroll
        for (int j = 0; j < 8; j++)
#pragma unroll
            for (int q = 0; q < 4; q++) sacc[j][q] = 0.f;
#pragma unroll
        for (int kc = 0; kc < 8; kc++) {
#pragma unroll
            for (int jh = 0; jh < 2; jh++) {
                uint32_t bh[4][2], bl[4][2];
#pragma unroll
                for (int jp = 0; jp < 2; jp++) {
                    uint32_t a = sbase
                        + (uint32_t)(((jh * 4 + jp * 2) * 8 + brow) * KSTR
                                     + kc * 16 + bcol) * 2;
                    ldsm4(bh[jp * 2][0], bh[jp * 2][1],
                          bh[jp * 2 + 1][0], bh[jp * 2 + 1][1], a);
                    ldsm4(bl[jp * 2][0], bl[jp * 2][1],
                          bl[jp * 2 + 1][0], bl[jp * 2 + 1][1], a + FSM_KL * 2);
                }
#pragma unroll
                for (int jj = 0; jj < 4; jj++) mma_bf16(sacc[jh * 4 + jj], qh[kc], bh[jj]);
#pragma unroll
                for (int jj = 0; jj < 4; jj++) mma_bf16(sacc[jh * 4 + jj], qh[kc], bl[jj]);
#pragma unroll
                for (int jj = 0; jj < 4; jj++) mma_bf16(sacc[jh * 4 + jj], ql[kc], bh[jj]);
            }
        }

        if (kt == qt) {
#pragma unroll
            for (int j = 0; j < 8; j++) {
#pragma unroll
                for (int q = 0; q < 4; q++) {
                    int col = kb0 + j * 8 + c2 + (q & 1);
                    int row = qrow + ((q >= 2) ? 8 : 0);
                    if (col > row) sacc[j][q] = -1e30f;
                }
            }
        }

#pragma unroll
        for (int g = 0; g < 2; g++) {
            float rm = -1e30f;
#pragma unroll
            for (int j = 0; j < 8; j++)
                rm = fmaxf(rm, fmaxf(sacc[j][2 * g], sacc[j][2 * g + 1]));
            rm *= SC;
            rm = fmaxf(rm, __shfl_xor_sync(0xffffffffu, rm, 1));
            rm = fmaxf(rm, __shfl_xor_sync(0xffffffffu, rm, 2));
            float mn = fmaxf(m2[g], rm);
            float alpha = exp2f(m2[g] - mn);
            m2[g] = mn;
            float rs = 0.f;
#pragma unroll
            for (int j = 0; j < 8; j++) {
#pragma unroll
                for (int q = 2 * g; q < 2 * g + 2; q++) {
                    float p = exp2f(sacc[j][q] * SC - mn);
                    sacc[j][q] = p;
                    rs += p;
                }
            }
            rs += __shfl_xor_sync(0xffffffffu, rs, 1);
            rs += __shfl_xor_sync(0xffffffffu, rs, 2);
            l[g] = l[g] * alpha + rs;
#pragma unroll
            for (int t = 0; t < 16; t++) {
                o[t][2 * g]     *= alpha;
                o[t][2 * g + 1] *= alpha;
            }
        }

#pragma unroll
        for (int kc2 = 0; kc2 < 4; kc2++) {
            uint32_t ph[4], pl[4];
            ph[0] = packbf(sacc[2 * kc2][0], sacc[2 * kc2][1]);
            ph[1] = packbf(sacc[2 * kc2][2], sacc[2 * kc2][3]);
            ph[2] = packbf(sacc[2 * kc2 + 1][0], sacc[2 * kc2 + 1][1]);
            ph[3] = packbf(sacc[2 * kc2 + 1][2], sacc[2 * kc2 + 1][3]);
            pl[0] = packbf_res(ph[0], sacc[2 * kc2][0], sacc[2 * kc2][1]);
            pl[1] = packbf_res(ph[1], sacc[2 * kc2][2], sacc[2 * kc2][3]);
            pl[2] = packbf_res(ph[2], sacc[2 * kc2 + 1][0], sacc[2 * kc2 + 1][1]);
            pl[3] = packbf_res(ph[3], sacc[2 * kc2 + 1][2], sacc[2 * kc2 + 1][3]);
#pragma unroll
            for (int jg = 0; jg < 4; jg++) {
                uint32_t vh[4][2], vl[4][2];
#pragma unroll
                for (int jp = 0; jp < 2; jp++) {
                    uint32_t a = sbase + FSM_VH * 2
                        + (uint32_t)(((jg * 4 + jp * 2) * 8 + brow) * VSTR
                                     + kc2 * 16 + bcol) * 2;
                    ldsm4(vh[jp * 2][0], vh[jp * 2][1],
                          vh[jp * 2 + 1][0], vh[jp * 2 + 1][1], a);
                    ldsm4(vl[jp * 2][0], vl[jp * 2][1],
                          vl[jp * 2 + 1][0], vl[jp * 2 + 1][1],
                          a + (FSM_VL - FSM_VH) * 2);
                }
#pragma unroll
                for (int jj = 0; jj < 4; jj++) mma_bf16(o[jg * 4 + jj], ph, vh[jj]);
#pragma unroll
                for (int jj = 0; jj < 4; jj++) mma_bf16(o[jg * 4 + jj], ph, vl[jj]);
#pragma unroll
                for (int jj = 0; jj < 4; jj++) mma_bf16(o[jg * 4 + jj], pl, vh[jj]);
            }
        }
    }

    float inv0 = 1.f / l[0], inv1 = 1.f / l[1];
#pragma unroll
    for (int jd = 0; jd < 16; jd++) {
        int col = h * HS + jd * 8 + c2;
        {
            float v0 = o[jd][0] * inv0, v1 = o[jd][1] * inv0;
            uint32_t hp = packbf(v0, v1);
            uint32_t lp = packbf_res(hp, v0, v1);
            *reinterpret_cast<uint32_t*>(g_ATh + (size_t)qrow * HID + col) = hp;
            *reinterpret_cast<uint32_t*>(g_ATl + (size_t)qrow * HID + col) = lp;
        }
        {
            float v0 = o[jd][2] * inv1, v1 = o[jd][3] * inv1;
            uint32_t hp = packbf(v0, v1);
            uint32_t lp = packbf_res(hp, v0, v1);
            *reinterpret_cast<uint32_t*>(g_ATh + (size_t)(qrow + 8) * HID + col) = hp;
            *reinterpret_cast<uint32_t*>(g_ATl + (size_t)(qrow + 8) * HID + col) = lp;
        }
    }
}

// ---------------------------------------------------------------------------
extern "C" void kernel_launch(void* const* d_in, const int* in_sizes, int n_in,
                              void* d_out, int out_size)
{
    (void)in_sizes; (void)n_in; (void)out_size;
    const float* hidden = (const float*)d_in[0];
    const float* qkvk = (const float*)d_in[2];
    const float* qkvb = (const float*)d_in[3];
    const float* outk = (const float*)d_in[4];
    const float* outb = (const float*)d_in[5];
    float* out = (float*)d_out;

    cudaFuncSetAttribute(gemm_mma, cudaFuncAttributeMaxDynamicSharedMemorySize, GEMM_SMEM);
    cudaFuncSetAttribute(flash_mma, cudaFuncAttributeMaxDynamicSharedMemorySize, FLASH_SMEM);

    void *Ah, *Al, *Bqh, *Bql, *Boh, *Bol, *ATh, *ATl;
    cudaGetSymbolAddress(&Ah, g_Ah);   cudaGetSymbolAddress(&Al, g_Al);
    cudaGetSymbolAddress(&Bqh, g_Bqh); cudaGetSymbolAddress(&Bql, g_Bql);
    cudaGetSymbolAddress(&Boh, g_Boh); cudaGetSymbolAddress(&Bol, g_Bol);
    cudaGetSymbolAddress(&ATh, g_ATh); cudaGetSymbolAddress(&ATl, g_ATl);

    conv_split<<<(S_LEN * HID) / 1024, 256>>>(
        (const float4*)hidden, (__nv_bfloat162*)Ah, (__nv_bfloat162*)Al);
    conv_transpose_split<<<dim3(QKV_N / 32, HID / 32), 256>>>(
        qkvk, (__nv_bfloat16*)Bqh, (__nv_bfloat16*)Bql, HID, QKV_N);
    conv_transpose_split<<<dim3(HID / 32, HID / 32), 256>>>(
        outk, (__nv_bfloat16*)Boh, (__nv_bfloat16*)Bol, HID, HID);

    // QKV projection + fused rotary + Q/K split (V -> fp32)
    gemm_mma<<<dim3(QKV_N / 128, S_LEN / 64), 128, GEMM_SMEM>>>(
        (const __nv_bfloat16*)Ah, (const __nv_bfloat16*)Al,
        (const __nv_bfloat16*)Bqh, (const __nv_bfloat16*)Bql,
        qkvb, QKV_N, nullptr, 0);

    vtrans<<<dim3(S_LEN / 32, HS / 32, NHEADS), 256>>>();

    flash_mma<<<dim3(S_LEN / 64, NHEADS), 128, FLASH_SMEM>>>();

    gemm_mma<<<dim3(HID / 128, S_LEN / 64), 128, GEMM_SMEM>>>(
        (const __nv_bfloat16*)ATh, (const __nv_bfloat16*)ATl,
        (const __nv_bfloat16*)Boh, (const __nv_bfloat16*)Bol,
        outb, HID, out, 1);
}

// round 10
// speedup vs baseline: 1.0573x; 1.0368x over previous
#include <cuda_runtime.h>
#include <cuda_bf16.h>
#include <math.h>
#include <stdint.h>

#define S_LEN  2048
#define HID    2048
#define NHEADS 16
#define HS     128
#define QKV_N  6144
#define KTOT   2048
#define INV_NORM 0.08838834764831845f

// ---------------- scratch (device globals; no allocations allowed) ----------
__device__ __nv_bfloat16 g_Ah[(size_t)S_LEN * HID];
__device__ __nv_bfloat16 g_Al[(size_t)S_LEN * HID];
__device__ __nv_bfloat16 g_Bqh[(size_t)QKV_N * HID];
__device__ __nv_bfloat16 g_Bql[(size_t)QKV_N * HID];
__device__ __nv_bfloat16 g_Boh[(size_t)HID * HID];
__device__ __nv_bfloat16 g_Bol[(size_t)HID * HID];
__device__ __nv_bfloat16 g_ATh[(size_t)S_LEN * HID];
__device__ __nv_bfloat16 g_ATl[(size_t)S_LEN * HID];
__device__ __nv_bfloat16 g_Qh[(size_t)NHEADS * S_LEN * HS];
__device__ __nv_bfloat16 g_Ql[(size_t)NHEADS * S_LEN * HS];
__device__ __nv_bfloat16 g_Kh[(size_t)NHEADS * S_LEN * HS];
__device__ __nv_bfloat16 g_Kl[(size_t)NHEADS * S_LEN * HS];
__device__ __nv_bfloat16 g_Vh[(size_t)NHEADS * S_LEN * HS];   // V [h][s][d] hi
__device__ __nv_bfloat16 g_Vl[(size_t)NHEADS * S_LEN * HS];   // V [h][s][d] lo

// exact fp32 roundings of 10000^(-j/16) = 10^(-j/4)
__device__ __constant__ float c_invfreq[16] = {
    1.0f, 0.5623413251903491f, 0.31622776601683794f, 0.17782794100389228f,
    0.1f, 0.05623413251903491f, 0.03162277660168379f, 0.017782794100389228f,
    0.01f, 0.005623413251903491f, 0.0031622776601683794f, 0.0017782794100389228f,
    0.001f, 0.0005623413251903491f, 0.00031622776601683794f, 0.00017782794100389228f
};

// ------------------------------- helpers ------------------------------------
__device__ __forceinline__ uint32_t smem_to_u32(const void* p) {
    uint32_t a;
    asm("{ .reg .u64 t; cvta.to.shared.u64 t, %1; cvt.u32.u64 %0, t; }"
        : "=r"(a) : "l"(p));
    return a;
}
__device__ __forceinline__ void cp_async16(uint32_t dst, const void* src) {
    asm volatile("cp.async.cg.shared.global [%0], [%1], 16;"
                 :: "r"(dst), "l"(src) : "memory");
}
#define CP_COMMIT() asm volatile("cp.async.commit_group;" ::: "memory")
#define CP_WAIT(n)  asm volatile("cp.async.wait_group %0;" :: "n"(n) : "memory")

__device__ __forceinline__ void mma_bf16(float* c, const uint32_t* a, const uint32_t* b) {
    asm volatile(
        "mma.sync.aligned.m16n8k16.row.col.f32.bf16.bf16.f32 "
        "{%0,%1,%2,%3}, {%4,%5,%6,%7}, {%8,%9}, {%0,%1,%2,%3};"
        : "+f"(c[0]), "+f"(c[1]), "+f"(c[2]), "+f"(c[3])
        : "r"(a[0]), "r"(a[1]), "r"(a[2]), "r"(a[3]), "r"(b[0]), "r"(b[1]));
}
__device__ __forceinline__ void ldsm4(uint32_t& r0, uint32_t& r1, uint32_t& r2,
                                      uint32_t& r3, uint32_t addr) {
    asm volatile("ldmatrix.sync.aligned.m8n8.x4.shared.b16 {%0,%1,%2,%3}, [%4];"
        : "=r"(r0), "=r"(r1), "=r"(r2), "=r"(r3) : "r"(addr));
}
__device__ __forceinline__ void ldsm4t(uint32_t& r0, uint32_t& r1, uint32_t& r2,
                                       uint32_t& r3, uint32_t addr) {
    asm volatile("ldmatrix.sync.aligned.m8n8.x4.trans.shared.b16 {%0,%1,%2,%3}, [%4];"
        : "=r"(r0), "=r"(r1), "=r"(r2), "=r"(r3) : "r"(addr));
}
__device__ __forceinline__ uint32_t packbf(float lo, float hi) {
    uint32_t d;
    asm("cvt.rn.bf16x2.f32 %0, %1, %2;" : "=r"(d) : "f"(hi), "f"(lo));
    return d;
}
__device__ __forceinline__ uint32_t packbf_res(uint32_t hpack, float lo, float hi) {
    float rl = lo - __uint_as_float(hpack << 16);
    float rh = hi - __uint_as_float(hpack & 0xffff0000u);
    return packbf(rl, rh);
}

// ---------------------------------------------------------------------------
// Conversion kernels
// ---------------------------------------------------------------------------
__global__ __launch_bounds__(256) void conv_split(
    const float4* __restrict__ X, __nv_bfloat162* __restrict__ H,
    __nv_bfloat162* __restrict__ L)
{
    int i = blockIdx.x * 256 + threadIdx.x;
    float4 v = X[i];
    __nv_bfloat16 h0 = __float2bfloat16_rn(v.x), h1 = __float2bfloat16_rn(v.y);
    __nv_bfloat16 h2 = __float2bfloat16_rn(v.z), h3 = __float2bfloat16_rn(v.w);
    __nv_bfloat16 l0 = __float2bfloat16_rn(v.x - __bfloat162float(h0));
    __nv_bfloat16 l1 = __float2bfloat16_rn(v.y - __bfloat162float(h1));
    __nv_bfloat16 l2 = __float2bfloat16_rn(v.z - __bfloat162float(h2));
    __nv_bfloat16 l3 = __float2bfloat16_rn(v.w - __bfloat162float(h3));
    H[2 * i] = __halves2bfloat162(h0, h1); H[2 * i + 1] = __halves2bfloat162(h2, h3);
    L[2 * i] = __halves2bfloat162(l0, l1); L[2 * i + 1] = __halves2bfloat162(l2, l3);
}

__global__ __launch_bounds__(256) void conv_transpose_split(
    const float* __restrict__ B, __nv_bfloat16* __restrict__ H,
    __nv_bfloat16* __restrict__ L, int K, int N)
{
    __shared__ float t[32][33];
    int x = threadIdx.x & 31, y = threadIdx.x >> 5;
    int n0 = blockIdx.x * 32, k0 = blockIdx.y * 32;
#pragma unroll
    for (int j = 0; j < 32; j += 8)
        t[y + j][x] = B[(size_t)(k0 + y + j) * N + n0 + x];
    __syncthreads();
#pragma unroll
    for (int j = 0; j < 32; j += 8) {
        float v = t[x][y + j];
        __nv_bfloat16 h = __float2bfloat16_rn(v);
        __nv_bfloat16 l = __float2bfloat16_rn(v - __bfloat162float(h));
        size_t o = (size_t)(n0 + y + j) * K + k0 + x;
        H[o] = h; L[o] = l;
    }
}

// ---------------------------------------------------------------------------
// bf16x3 mma.sync GEMM. BM=64, BN=128, BK=32, 128 threads, 3-stage pipeline,
// 2 CTAs/SM (the R6 best-known config).
// mode 0 epilogue: fused rotary + Q/K/V bf16 hi/lo split.
// ---------------------------------------------------------------------------
#define GBK 32
#define GNITER (KTOT / GBK)
#define ROWSTR 40
#define A_BUFH (64 * ROWSTR)
#define B_BUFH (128 * ROWSTR)
#define ST_AH 0
#define ST_AL A_BUFH
#define ST_BH (2 * A_BUFH)
#define ST_BL (2 * A_BUFH + B_BUFH)
#define STGH  (2 * A_BUFH + 2 * B_BUFH)   // 15360 halves = 30720 B
#define GSTAGES 3
#define GEMM_SMEM (GSTAGES * STGH * 2)    // 92160 B

__global__ __launch_bounds__(128, 2) void gemm_mma(
    const __nv_bfloat16* __restrict__ Ah, const __nv_bfloat16* __restrict__ Al,
    const __nv_bfloat16* __restrict__ Bh, const __nv_bfloat16* __restrict__ Bl,
    const float* __restrict__ bias, int N, float* __restrict__ Cout, int mode)
{
    extern __shared__ __align__(16) __nv_bfloat16 sm[];
    const int tid = threadIdx.x;
    const int wn = tid >> 5, lane = tid & 31;
    const int n0 = blockIdx.x * 128, m0 = blockIdx.y * 64;
    const uint32_t sbase = smem_to_u32(sm);

    const int r  = lane >> 2;
    const int c2 = (lane & 3) * 2;
    const int arow = ((lane >> 3) & 1) * 8 + (lane & 7);
    const int acol = (lane >> 4) * 8;
    const int brow = ((lane >> 4) & 1) * 8 + (lane & 7);
    const int bcol = ((lane >> 3) & 1) * 8;

    float acc[4][4][4];
#pragma unroll
    for (int i = 0; i < 4; i++)
#pragma unroll
        for (int j = 0; j < 4; j++)
#pragma unroll
            for (int q = 0; q < 4; q++) acc[i][j][q] = 0.f;

    auto load_stage = [&](int s, int k0) {
        const uint32_t st = sbase + (uint32_t)s * STGH * 2;
#pragma unroll
        for (int i = 0; i < 2; i++) {
            int c = tid + i * 128;
            int row = c >> 2, kc = c & 3;
            uint32_t doff = (uint32_t)(row * ROWSTR + kc * 8) * 2;
            size_t go = (size_t)(m0 + row) * KTOT + k0 + kc * 8;
            cp_async16(st + ST_AH * 2 + doff, Ah + go);
            cp_async16(st + ST_AL * 2 + doff, Al + go);
        }
#pragma unroll
        for (int i = 0; i < 4; i++) {
            int c = tid + i * 128;
            int row = c >> 2, kc = c & 3;
            uint32_t doff = (uint32_t)(row * ROWSTR + kc * 8) * 2;
            size_t go = (size_t)(n0 + row) * KTOT + k0 + kc * 8;
            cp_async16(st + ST_BH * 2 + doff, Bh + go);
            cp_async16(st + ST_BL * 2 + doff, Bl + go);
        }
    };

    load_stage(0, 0); CP_COMMIT();
    load_stage(1, GBK); CP_COMMIT();

    for (int it = 0; it < GNITER; it++) {
        const int s = it % GSTAGES;
        if (it < GNITER - 1) { CP_WAIT(1); } else { CP_WAIT(0); }
        __syncthreads();

        const uint32_t stg = sbase + (uint32_t)s * STGH * 2;

#pragma unroll
        for (int ks = 0; ks < 2; ks++) {
            uint32_t ah[4][4], al[4][4], bh[4][2], bl[4][2];
#pragma unroll
            for (int i = 0; i < 4; i++) {
                uint32_t a = stg + (uint32_t)((i * 16 + arow) * ROWSTR
                                              + ks * 16 + acol) * 2;
                ldsm4(ah[i][0], ah[i][1], ah[i][2], ah[i][3], a + ST_AH * 2);
                ldsm4(al[i][0], al[i][1], al[i][2], al[i][3], a + ST_AL * 2);
            }
#pragma unroll
            for (int jp = 0; jp < 2; jp++) {
                uint32_t b = stg + (uint32_t)((wn * 32 + jp * 16 + brow) * ROWSTR
                                              + ks * 16 + bcol) * 2;
                ldsm4(bh[jp * 2][0], bh[jp * 2][1], bh[jp * 2 + 1][0], bh[jp * 2 + 1][1],
                      b + ST_BH * 2);
                ldsm4(bl[jp * 2][0], bl[jp * 2][1], bl[jp * 2 + 1][0], bl[jp * 2 + 1][1],
                      b + ST_BL * 2);
            }
#pragma unroll
            for (int i = 0; i < 4; i++)
#pragma unroll
                for (int j = 0; j < 4; j++) mma_bf16(acc[i][j], ah[i], bh[j]);
#pragma unroll
            for (int i = 0; i < 4; i++)
#pragma unroll
                for (int j = 0; j < 4; j++) mma_bf16(acc[i][j], ah[i], bl[j]);
#pragma unroll
            for (int i = 0; i < 4; i++)
#pragma unroll
                for (int j = 0; j < 4; j++) mma_bf16(acc[i][j], al[i], bh[j]);
        }
        if (it + 2 < GNITER) {
            load_stage((it + 2) % GSTAGES, (it + 2) * GBK);
            CP_COMMIT();
        }
    }

#pragma unroll
    for (int i = 0; i < 4; i++) {
#pragma unroll
        for (int j = 0; j < 4; j++) {
            int n = n0 + wn * 32 + j * 8 + c2;
            float2 bv = *reinterpret_cast<const float2*>(bias + n);
#pragma unroll
            for (int half = 0; half < 2; half++) {
                int m = m0 + i * 16 + r + half * 8;
                float2 v = make_float2(acc[i][j][half * 2] + bv.x,
                                       acc[i][j][half * 2 + 1] + bv.y);
                if (mode) {
                    *reinterpret_cast<float2*>(Cout + (size_t)m * N + n) = v;
                } else {
                    int h = n / 384, e = n - h * 384;
                    int seg = e >> 7, d = e & 127;
                    if (seg < 2 && d < 32) {   // fused rotary: partner acc[i][j±2]
                        bool low = d < 16;
                        int jp = low ? j + 2 : j - 2;
                        int np = low ? n + 16 : n - 16;
                        float2 bvp = *reinterpret_cast<const float2*>(bias + np);
                        float px = acc[i][jp][half * 2] + bvp.x;
                        float py = acc[i][jp][half * 2 + 1] + bvp.y;
                        float f0 = (float)m * c_invfreq[d & 15];
                        float f1 = (float)m * c_invfreq[(d + 1) & 15];
                        float s0, c0, s1, c1;
                        sincosf(f0, &s0, &c0);
                        sincosf(f1, &s1, &c1);
                        if (low) { v.x = v.x * c0 - px * s0; v.y = v.y * c1 - py * s1; }
                        else     { v.x = v.x * c0 + px * s0; v.y = v.y * c1 + py * s1; }
                    }
                    uint32_t hp = packbf(v.x, v.y);
                    uint32_t lp = packbf_res(hp, v.x, v.y);
                    size_t off = ((size_t)h * S_LEN + m) * HS + d;
                    if (seg == 0) {
                        *reinterpret_cast<uint32_t*>(g_Qh + off) = hp;
                        *reinterpret_cast<uint32_t*>(g_Ql + off) = lp;
                    } else if (seg == 1) {
                        *reinterpret_cast<uint32_t*>(g_Kh + off) = hp;
                        *reinterpret_cast<uint32_t*>(g_Kl + off) = lp;
                    } else {
                        *reinterpret_cast<uint32_t*>(g_Vh + off) = hp;
                        *reinterpret_cast<uint32_t*>(g_Vl + off) = lp;
                    }
                }
            }
        }
    }
}

// ---------------------------------------------------------------------------
// Flash attention, mma.sync bf16x3. K,V both [s][d] in smem (pitch 136).
// V B-fragments via ldmatrix.trans. K/V loads software-pipelined.
// ---------------------------------------------------------------------------
#define KSTR 136
#define SM_KH 0
#define SM_KL (64 * KSTR)
#define SM_VH (2 * 64 * KSTR)
#define SM_VL (3 * 64 * KSTR)
#define FLASH_SMEM (4 * 64 * KSTR * 2)    // 69632 B -> 2 CTAs/SM

__global__ __launch_bounds__(128, 2) void flash_mma()
{
    const int h  = blockIdx.y;
    const int qt = (gridDim.x - 1) - blockIdx.x;
    const int q0 = qt * 64;

    extern __shared__ __align__(16) __nv_bfloat16 fsm[];
    const uint32_t sbase = smem_to_u32(fsm);

    const int tid = threadIdx.x;
    const int w = tid >> 5, lane = tid & 31;
    const int r = lane >> 2, c2 = (lane & 3) * 2;
    const int brow = ((lane >> 4) & 1) * 8 + (lane & 7);
    const int bcol = ((lane >> 3) & 1) * 8;
    const int trow = lane & 15;                 // trans-ldsm row (k = s index)
    const int tcol = ((lane >> 4) & 1) * 8;     // trans-ldsm col half (d)
    const int qrow = q0 + w * 16 + r;

    const __nv_bfloat16* Qhg = g_Qh + (size_t)h * S_LEN * HS;
    const __nv_bfloat16* Qlg = g_Ql + (size_t)h * S_LEN * HS;
    const __nv_bfloat16* Khg = g_Kh + (size_t)h * S_LEN * HS;
    const __nv_bfloat16* Klg = g_Kl + (size_t)h * S_LEN * HS;
    const __nv_bfloat16* Vhg = g_Vh + (size_t)h * S_LEN * HS;
    const __nv_bfloat16* Vlg = g_Vl + (size_t)h * S_LEN * HS;

    auto load_K = [&](int kt) {
        const int kb0 = kt * 64;
#pragma unroll
        for (int i = 0; i < 8; i++) {
            int c = i * 128 + tid;
            int row = c >> 4, col = c & 15;
            uint32_t dof = (uint32_t)(row * KSTR + col * 8) * 2;
            size_t g = (size_t)(kb0 + row) * HS + col * 8;
            cp_async16(sbase + SM_KH * 2 + dof, Khg + g);
            cp_async16(sbase + SM_KL * 2 + dof, Klg + g);
        }
    };
    auto load_V = [&](int kt) {
        const int kb0 = kt * 64;
#pragma unroll
        for (int i = 0; i < 8; i++) {
            int c = i * 128 + tid;
            int row = c >> 4, col = c & 15;
            uint32_t dof = (uint32_t)(row * KSTR + col * 8) * 2;
            size_t g = (size_t)(kb0 + row) * HS + col * 8;
            cp_async16(sbase + SM_VH * 2 + dof, Vhg + g);
            cp_async16(sbase + SM_VL * 2 + dof, Vlg + g);
        }
    };

    // preload Q fragments (registers)
    uint32_t qh[8][4], ql[8][4];
#pragma unroll
    for (int kc = 0; kc < 8; kc++) {
        size_t o0 = (size_t)qrow * HS + kc * 16 + c2;
        size_t o1 = (size_t)(qrow + 8) * HS + kc * 16 + c2;
        qh[kc][0] = *reinterpret_cast<const uint32_t*>(Qhg + o0);
        qh[kc][1] = *reinterpret_cast<const uint32_t*>(Qhg + o1);
        qh[kc][2] = *reinterpret_cast<const uint32_t*>(Qhg + o0 + 8);
        qh[kc][3] = *reinterpret_cast<const uint32_t*>(Qhg + o1 + 8);
        ql[kc][0] = *reinterpret_cast<const uint32_t*>(Qlg + o0);
        ql[kc][1] = *reinterpret_cast<const uint32_t*>(Qlg + o1);
        ql[kc][2] = *reinterpret_cast<const uint32_t*>(Qlg + o0 + 8);
        ql[kc][3] = *reinterpret_cast<const uint32_t*>(Qlg + o1 + 8);
    }

    load_K(0); CP_COMMIT();
    load_V(0); CP_COMMIT();

    float o[16][4];
#pragma unroll
    for (int t = 0; t < 16; t++)
#pragma unroll
        for (int q = 0; q < 4; q++) o[t][q] = 0.f;
    float m2[2] = {-1e30f, -1e30f};
    float l[2] = {0.f, 0.f};

    const float SC = INV_NORM * 1.4426950408889634f;

    for (int kt = 0; kt <= qt; kt++) {
        const int kb0 = kt * 64;
        CP_WAIT(1);              // K(kt) landed (V(kt) may be in flight)
        __syncthreads();

        // ---- S = Q K^T ----
        float sacc[8][4];
#pragma unroll
        for (int j = 0; j < 8; j++)
#pragma unroll
            for (int q = 0; q < 4; q++) sacc[j][q] = 0.f;
#pragma unroll
        for (int kc = 0; kc < 8; kc++) {
#pragma unroll
            for (int jh = 0; jh < 2; jh++) {
                uint32_t bh[4][2], bl[4][2];
#pragma unroll
                for (int jp = 0; jp < 2; jp++) {
                    uint32_t a = sbase
                        + (uint32_t)(((jh * 4 + jp * 2) * 8 + brow) * KSTR
                                     + kc * 16 + bcol) * 2;
                    ldsm4(bh[jp * 2][0], bh[jp * 2][1],
                          bh[jp * 2 + 1][0], bh[jp * 2 + 1][1], a + SM_KH * 2);
                    ldsm4(bl[jp * 2][0], bl[jp * 2][1],
                          bl[jp * 2 + 1][0], bl[jp * 2 + 1][1], a + SM_KL * 2);
                }
#pragma unroll
                for (int jj = 0; jj < 4; jj++) mma_bf16(sacc[jh * 4 + jj], qh[kc], bh[jj]);
#pragma unroll
                for (int jj = 0; jj < 4; jj++) mma_bf16(sacc[jh * 4 + jj], qh[kc], bl[jj]);
#pragma unroll
                for (int jj = 0; jj < 4; jj++) mma_bf16(sacc[jh * 4 + jj], ql[kc], bh[jj]);
            }
        }

        if (kt == qt) {           // causal mask, diagonal tile
#pragma unroll
            for (int j = 0; j < 8; j++) {
#pragma unroll
                for (int q = 0; q < 4; q++) {
                    int col = kb0 + j * 8 + c2 + (q & 1);
                    int row = qrow + ((q >= 2) ? 8 : 0);
                    if (col > row) sacc[j][q] = -1e30f;
                }
            }
        }

        // ---- online softmax (register-only; V load drains meanwhile) ----
#pragma unroll
        for (int g = 0; g < 2; g++) {
            float rm = -1e30f;
#pragma unroll
            for (int j = 0; j < 8; j++)
                rm = fmaxf(rm, fmaxf(sacc[j][2 * g], sacc[j][2 * g + 1]));
            rm *= SC;
            rm = fmaxf(rm, __shfl_xor_sync(0xffffffffu, rm, 1));
            rm = fmaxf(rm, __shfl_xor_sync(0xffffffffu, rm, 2));
            float mn = fmaxf(m2[g], rm);
            float alpha = exp2f(m2[g] - mn);
            m2[g] = mn;
            float rs = 0.f;
#pragma unroll
            for (int j = 0; j < 8; j++) {
#pragma unroll
                for (int q = 2 * g; q < 2 * g + 2; q++) {
                    float p = exp2f(sacc[j][q] * SC - mn);
                    sacc[j][q] = p;
                    rs += p;
                }
            }
            rs += __shfl_xor_sync(0xffffffffu, rs, 1);
            rs += __shfl_xor_sync(0xffffffffu, rs, 2);
            l[g] = l[g] * alpha + rs;
#pragma unroll
            for (int t = 0; t < 16; t++) {
                o[t][2 * g]     *= alpha;
                o[t][2 * g + 1] *= alpha;
            }
        }

        __syncthreads();          // all warps done reading sK
        const bool more = (kt + 1 <= qt);
        if (more) { load_K(kt + 1); CP_COMMIT(); CP_WAIT(1); }
        else      { CP_WAIT(0); }
        __syncthreads();          // V(kt) visible to all

        // ---- O += P V  (V fragments via ldmatrix.trans from [s][d]) ----
#pragma unroll
        for (int kc2 = 0; kc2 < 4; kc2++) {
            uint32_t ph[4], pl[4];
            ph[0] = packbf(sacc[2 * kc2][0], sacc[2 * kc2][1]);
            ph[1] = packbf(sacc[2 * kc2][2], sacc[2 * kc2][3]);
            ph[2] = packbf(sacc[2 * kc2 + 1][0], sacc[2 * kc2 + 1][1]);
            ph[3] = packbf(sacc[2 * kc2 + 1][2], sacc[2 * kc2 + 1][3]);
            pl[0] = packbf_res(ph[0], sacc[2 * kc2][0], sacc[2 * kc2][1]);
            pl[1] = packbf_res(ph[1], sacc[2 * kc2][2], sacc[2 * kc2][3]);
            pl[2] = packbf_res(ph[2], sacc[2 * kc2 + 1][0], sacc[2 * kc2 + 1][1]);
            pl[3] = packbf_res(ph[3], sacc[2 * kc2 + 1][2], sacc[2 * kc2 + 1][3]);
#pragma unroll
            for (int jg = 0; jg < 8; jg++) {   // d16 chunks
                uint32_t a = sbase
                    + (uint32_t)((kc2 * 16 + trow) * KSTR + jg * 16 + tcol) * 2;
                uint32_t vh[2][2], vl[2][2];
                ldsm4t(vh[0][0], vh[0][1], vh[1][0], vh[1][1], a + SM_VH * 2);
                ldsm4t(vl[0][0], vl[0][1], vl[1][0], vl[1][1], a + SM_VL * 2);
#pragma unroll
                for (int jj = 0; jj < 2; jj++) mma_bf16(o[jg * 2 + jj], ph, vh[jj]);
#pragma unroll
                for (int jj = 0; jj < 2; jj++) mma_bf16(o[jg * 2 + jj], ph, vl[jj]);
#pragma unroll
                for (int jj = 0; jj < 2; jj++) mma_bf16(o[jg * 2 + jj], pl, vh[jj]);
            }
        }

        if (more) {
            __syncthreads();      // all warps done reading sV
            load_V(kt + 1); CP_COMMIT();
        }
    }

    float inv0 = 1.f / l[0], inv1 = 1.f / l[1];
#pragma unroll
    for (int jd = 0; jd < 16; jd++) {
        int col = h * HS + jd * 8 + c2;
        {
            float v0 = o[jd][0] * inv0, v1 = o[jd][1] * inv0;
            uint32_t hp = packbf(v0, v1);
            uint32_t lp = packbf_res(hp, v0, v1);
            *reinterpret_cast<uint32_t*>(g_ATh + (size_t)qrow * HID + col) = hp;
            *reinterpret_cast<uint32_t*>(g_ATl + (size_t)qrow * HID + col) = lp;
        }
        {
            float v0 = o[jd][2] * inv1, v1 = o[jd][3] * inv1;
            uint32_t hp = packbf(v0, v1);
            uint32_t lp = packbf_res(hp, v0, v1);
            *reinterpret_cast<uint32_t*>(g_ATh + (size_t)(qrow + 8) * HID + col) = hp;
            *reinterpret_cast<uint32_t*>(g_ATl + (size_t)(qrow + 8) * HID + col) = lp;
        }
    }
}

// ---------------------------------------------------------------------------
extern "C" void kernel_launch(void* const* d_in, const int* in_sizes, int n_in,
                              void* d_out, int out_size)
{
    (void)in_sizes; (void)n_in; (void)out_size;
    const float* hidden = (const float*)d_in[0];
    const float* qkvk = (const float*)d_in[2];
    const float* qkvb = (const float*)d_in[3];
    const float* outk = (const float*)d_in[4];
    const float* outb = (const float*)d_in[5];
    float* out = (float*)d_out;

    cudaFuncSetAttribute(gemm_mma, cudaFuncAttributeMaxDynamicSharedMemorySize, GEMM_SMEM);
    cudaFuncSetAttribute(flash_mma, cudaFuncAttributeMaxDynamicSharedMemorySize, FLASH_SMEM);

    void *Ah, *Al, *Bqh, *Bql, *Boh, *Bol, *ATh, *ATl;
    cudaGetSymbolAddress(&Ah, g_Ah);   cudaGetSymbolAddress(&Al, g_Al);
    cudaGetSymbolAddress(&Bqh, g_Bqh); cudaGetSymbolAddress(&Bql, g_Bql);
    cudaGetSymbolAddress(&Boh, g_Boh); cudaGetSymbolAddress(&Bol, g_Bol);
    cudaGetSymbolAddress(&ATh, g_ATh); cudaGetSymbolAddress(&ATl, g_ATl);

    conv_split<<<(S_LEN * HID) / 1024, 256>>>(
        (const float4*)hidden, (__nv_bfloat162*)Ah, (__nv_bfloat162*)Al);
    conv_transpose_split<<<dim3(QKV_N / 32, HID / 32), 256>>>(
        qkvk, (__nv_bfloat16*)Bqh, (__nv_bfloat16*)Bql, HID, QKV_N);
    conv_transpose_split<<<dim3(HID / 32, HID / 32), 256>>>(
        outk, (__nv_bfloat16*)Boh, (__nv_bfloat16*)Bol, HID, HID);

    // QKV projection + fused rotary + Q/K/V hi/lo split
    gemm_mma<<<dim3(QKV_N / 128, S_LEN / 64), 128, GEMM_SMEM>>>(
        (const __nv_bfloat16*)Ah, (const __nv_bfloat16*)Al,
        (const __nv_bfloat16*)Bqh, (const __nv_bfloat16*)Bql,
        qkvb, QKV_N, nullptr, 0);

    // causal flash attention (pipelined K/V, trans-ldsm V)
    flash_mma<<<dim3(S_LEN / 64, NHEADS), 128, FLASH_SMEM>>>();

    // output projection
    gemm_mma<<<dim3(HID / 128, S_LEN / 64), 128, GEMM_SMEM>>>(
        (const __nv_bfloat16*)ATh, (const __nv_bfloat16*)ATl,
        (const __nv_bfloat16*)Boh, (const __nv_bfloat16*)Bol,
        outb, HID, out, 1);
}

// round 11
// speedup vs baseline: 1.5200x; 1.4377x over previous
#include <cuda_runtime.h>
#include <cuda_fp16.h>
#include <math.h>
#include <stdint.h>

#define S_LEN  2048
#define HID    2048
#define NHEADS 16
#define HS     128
#define QKV_N  6144
#define KTOT   2048
#define INV_NORM 0.08838834764831845f

// ---------------- scratch (device globals; no allocations allowed) ----------
__device__ __half g_Ah[(size_t)S_LEN * HID];      // hidden hi [m][k]
__device__ __half g_Al[(size_t)S_LEN * HID];      // hidden lo
__device__ __half g_Bq[(size_t)QKV_N * HID];      // qkv kernel^T single [n][k]
__device__ __half g_Bo[(size_t)HID * HID];        // out kernel^T single [n][k]
__device__ __half g_ATh[(size_t)S_LEN * HID];     // attn out hi
__device__ __half g_ATl[(size_t)S_LEN * HID];     // attn out lo
__device__ __half g_Qh[(size_t)NHEADS * S_LEN * HS];   // Q hi [h][s][d]
__device__ __half g_Ql[(size_t)NHEADS * S_LEN * HS];   // Q lo
__device__ __half g_Kk[(size_t)NHEADS * S_LEN * HS];   // K single
__device__ __half g_Vv[(size_t)NHEADS * S_LEN * HS];   // V single [h][s][d]

// exact fp32 roundings of 10000^(-j/16) = 10^(-j/4)
__device__ __constant__ float c_invfreq[16] = {
    1.0f, 0.5623413251903491f, 0.31622776601683794f, 0.17782794100389228f,
    0.1f, 0.05623413251903491f, 0.03162277660168379f, 0.017782794100389228f,
    0.01f, 0.005623413251903491f, 0.0031622776601683794f, 0.0017782794100389228f,
    0.001f, 0.0005623413251903491f, 0.00031622776601683794f, 0.00017782794100389228f
};

// ------------------------------- helpers ------------------------------------
__device__ __forceinline__ uint32_t smem_to_u32(const void* p) {
    uint32_t a;
    asm("{ .reg .u64 t; cvta.to.shared.u64 t, %1; cvt.u32.u64 %0, t; }"
        : "=r"(a) : "l"(p));
    return a;
}
__device__ __forceinline__ void cp_async16(uint32_t dst, const void* src) {
    asm volatile("cp.async.cg.shared.global [%0], [%1], 16;"
                 :: "r"(dst), "l"(src) : "memory");
}
#define CP_COMMIT() asm volatile("cp.async.commit_group;" ::: "memory")
#define CP_WAIT(n)  asm volatile("cp.async.wait_group %0;" :: "n"(n) : "memory")

__device__ __forceinline__ void mma_f16(float* c, const uint32_t* a, const uint32_t* b) {
    asm volatile(
        "mma.sync.aligned.m16n8k16.row.col.f32.f16.f16.f32 "
        "{%0,%1,%2,%3}, {%4,%5,%6,%7}, {%8,%9}, {%0,%1,%2,%3};"
        : "+f"(c[0]), "+f"(c[1]), "+f"(c[2]), "+f"(c[3])
        : "r"(a[0]), "r"(a[1]), "r"(a[2]), "r"(a[3]), "r"(b[0]), "r"(b[1]));
}
__device__ __forceinline__ void ldsm4(uint32_t& r0, uint32_t& r1, uint32_t& r2,
                                      uint32_t& r3, uint32_t addr) {
    asm volatile("ldmatrix.sync.aligned.m8n8.x4.shared.b16 {%0,%1,%2,%3}, [%4];"
        : "=r"(r0), "=r"(r1), "=r"(r2), "=r"(r3) : "r"(addr));
}
__device__ __forceinline__ void ldsm4t(uint32_t& r0, uint32_t& r1, uint32_t& r2,
                                       uint32_t& r3, uint32_t addr) {
    asm volatile("ldmatrix.sync.aligned.m8n8.x4.trans.shared.b16 {%0,%1,%2,%3}, [%4];"
        : "=r"(r0), "=r"(r1), "=r"(r2), "=r"(r3) : "r"(addr));
}
// pack two fp32 -> f16x2 (lo = first element, matching mma b32 layout)
__device__ __forceinline__ uint32_t packh(float lo, float hi) {
    uint32_t d;
    asm("cvt.rn.f16x2.f32 %0, %1, %2;" : "=r"(d) : "f"(hi), "f"(lo));
    return d;
}
__device__ __forceinline__ uint32_t packh_res(uint32_t hp, float lo, float hi) {
    __half2 h2 = *reinterpret_cast<__half2*>(&hp);
    float rl = lo - __low2float(h2);
    float rh = hi - __high2float(h2);
    return packh(rl, rh);
}

// ---------------------------------------------------------------------------
// Conversion kernels
// ---------------------------------------------------------------------------
__global__ __launch_bounds__(256) void conv_split(
    const float4* __restrict__ X, __half2* __restrict__ H, __half2* __restrict__ L)
{
    int i = blockIdx.x * 256 + threadIdx.x;
    float4 v = X[i];
    __half h0 = __float2half_rn(v.x), h1 = __float2half_rn(v.y);
    __half h2 = __float2half_rn(v.z), h3 = __float2half_rn(v.w);
    __half l0 = __float2half_rn(v.x - __half2float(h0));
    __half l1 = __float2half_rn(v.y - __half2float(h1));
    __half l2 = __float2half_rn(v.z - __half2float(h2));
    __half l3 = __float2half_rn(v.w - __half2float(h3));
    H[2 * i] = __halves2half2(h0, h1); H[2 * i + 1] = __halves2half2(h2, h3);
    L[2 * i] = __halves2half2(l0, l1); L[2 * i + 1] = __halves2half2(l2, l3);
}

__global__ __launch_bounds__(256) void conv_transpose_h(
    const float* __restrict__ B, __half* __restrict__ H, int K, int N)
{
    __shared__ float t[32][33];
    int x = threadIdx.x & 31, y = threadIdx.x >> 5;
    int n0 = blockIdx.x * 32, k0 = blockIdx.y * 32;
#pragma unroll
    for (int j = 0; j < 32; j += 8)
        t[y + j][x] = B[(size_t)(k0 + y + j) * N + n0 + x];
    __syncthreads();
#pragma unroll
    for (int j = 0; j < 32; j += 8)
        H[(size_t)(n0 + y + j) * K + k0 + x] = __float2half_rn(t[x][y + j]);
}

// ---------------------------------------------------------------------------
// fp16 asymmetric-split mma.sync GEMM: C = (Ah+Al)*B^T + bias, 2 MMAs/k-step.
// BM=64, BN=128, BK=32, 128 threads, 3-stage pipeline, 2 CTAs/SM.
// mode 0 epilogue: fused rotary + Q split / K single / V single.
// ---------------------------------------------------------------------------
#define GBK 32
#define GNITER (KTOT / GBK)
#define ROWSTR 40
#define A_BUFH (64 * ROWSTR)       // 2560 halves
#define B_BUFH (128 * ROWSTR)      // 5120 halves
#define ST_AH 0
#define ST_AL A_BUFH
#define ST_B  (2 * A_BUFH)
#define STGH  (2 * A_BUFH + B_BUFH)   // 10240 halves = 20480 B
#define GSTAGES 3
#define GEMM_SMEM (GSTAGES * STGH * 2)    // 61440 B

__global__ __launch_bounds__(128, 2) void gemm_mma(
    const __half* __restrict__ Ah, const __half* __restrict__ Al,
    const __half* __restrict__ Bw,
    const float* __restrict__ bias, int N, float* __restrict__ Cout, int mode)
{
    extern __shared__ __align__(16) __half sm[];
    const int tid = threadIdx.x;
    const int wn = tid >> 5, lane = tid & 31;
    const int n0 = blockIdx.x * 128, m0 = blockIdx.y * 64;
    const uint32_t sbase = smem_to_u32(sm);

    const int r  = lane >> 2;
    const int c2 = (lane & 3) * 2;
    const int arow = ((lane >> 3) & 1) * 8 + (lane & 7);
    const int acol = (lane >> 4) * 8;
    const int brow = ((lane >> 4) & 1) * 8 + (lane & 7);
    const int bcol = ((lane >> 3) & 1) * 8;

    float acc[4][4][4];
#pragma unroll
    for (int i = 0; i < 4; i++)
#pragma unroll
        for (int j = 0; j < 4; j++)
#pragma unroll
            for (int q = 0; q < 4; q++) acc[i][j][q] = 0.f;

    auto load_stage = [&](int s, int k0) {
        const uint32_t st = sbase + (uint32_t)s * STGH * 2;
#pragma unroll
        for (int i = 0; i < 2; i++) {               // A hi+lo: 256 chunks
            int c = tid + i * 128;
            int row = c >> 2, kc = c & 3;
            uint32_t doff = (uint32_t)(row * ROWSTR + kc * 8) * 2;
            size_t go = (size_t)(m0 + row) * KTOT + k0 + kc * 8;
            cp_async16(st + ST_AH * 2 + doff, Ah + go);
            cp_async16(st + ST_AL * 2 + doff, Al + go);
        }
#pragma unroll
        for (int i = 0; i < 4; i++) {               // B single: 512 chunks
            int c = tid + i * 128;
            int row = c >> 2, kc = c & 3;
            uint32_t doff = (uint32_t)(row * ROWSTR + kc * 8) * 2;
            size_t go = (size_t)(n0 + row) * KTOT + k0 + kc * 8;
            cp_async16(st + ST_B * 2 + doff, Bw + go);
        }
    };

    load_stage(0, 0); CP_COMMIT();
    load_stage(1, GBK); CP_COMMIT();

    for (int it = 0; it < GNITER; it++) {
        const int s = it % GSTAGES;
        if (it < GNITER - 1) { CP_WAIT(1); } else { CP_WAIT(0); }
        __syncthreads();

        const uint32_t stg = sbase + (uint32_t)s * STGH * 2;

#pragma unroll
        for (int ks = 0; ks < 2; ks++) {
            uint32_t ah[4][4], al[4][4], bh[4][2];
#pragma unroll
            for (int i = 0; i < 4; i++) {
                uint32_t a = stg + (uint32_t)((i * 16 + arow) * ROWSTR
                                              + ks * 16 + acol) * 2;
                ldsm4(ah[i][0], ah[i][1], ah[i][2], ah[i][3], a + ST_AH * 2);
                ldsm4(al[i][0], al[i][1], al[i][2], al[i][3], a + ST_AL * 2);
            }
#pragma unroll
            for (int jp = 0; jp < 2; jp++) {
                uint32_t b = stg + ST_B * 2
                           + (uint32_t)((wn * 32 + jp * 16 + brow) * ROWSTR
                                        + ks * 16 + bcol) * 2;
                ldsm4(bh[jp * 2][0], bh[jp * 2][1],
                      bh[jp * 2 + 1][0], bh[jp * 2 + 1][1], b);
            }
#pragma unroll
            for (int i = 0; i < 4; i++)
#pragma unroll
                for (int j = 0; j < 4; j++) mma_f16(acc[i][j], ah[i], bh[j]);
#pragma unroll
            for (int i = 0; i < 4; i++)
#pragma unroll
                for (int j = 0; j < 4; j++) mma_f16(acc[i][j], al[i], bh[j]);
        }
        if (it + 2 < GNITER) {
            load_stage((it + 2) % GSTAGES, (it + 2) * GBK);
            CP_COMMIT();
        }
    }

#pragma unroll
    for (int i = 0; i < 4; i++) {
#pragma unroll
        for (int j = 0; j < 4; j++) {
            int n = n0 + wn * 32 + j * 8 + c2;
            float2 bv = *reinterpret_cast<const float2*>(bias + n);
#pragma unroll
            for (int half = 0; half < 2; half++) {
                int m = m0 + i * 16 + r + half * 8;
                float2 v = make_float2(acc[i][j][half * 2] + bv.x,
                                       acc[i][j][half * 2 + 1] + bv.y);
                if (mode) {
                    *reinterpret_cast<float2*>(Cout + (size_t)m * N + n) = v;
                } else {
                    int h = n / 384, e = n - h * 384;
                    int seg = e >> 7, d = e & 127;
                    if (seg < 2 && d < 32) {   // fused rotary: partner acc[i][j±2]
                        bool low = d < 16;
                        int jp = low ? j + 2 : j - 2;
                        int np = low ? n + 16 : n - 16;
                        float2 bvp = *reinterpret_cast<const float2*>(bias + np);
                        float px = acc[i][jp][half * 2] + bvp.x;
                        float py = acc[i][jp][half * 2 + 1] + bvp.y;
                        float f0 = (float)m * c_invfreq[d & 15];
                        float f1 = (float)m * c_invfreq[(d + 1) & 15];
                        float s0, c0, s1, c1;
                        sincosf(f0, &s0, &c0);
                        sincosf(f1, &s1, &c1);
                        if (low) { v.x = v.x * c0 - px * s0; v.y = v.y * c1 - py * s1; }
                        else     { v.x = v.x * c0 + px * s0; v.y = v.y * c1 + py * s1; }
                    }
                    size_t off = ((size_t)h * S_LEN + m) * HS + d;
                    if (seg == 0) {          // Q: split (A-side of S)
                        uint32_t hp = packh(v.x, v.y);
                        *reinterpret_cast<uint32_t*>(g_Qh + off) = hp;
                        *reinterpret_cast<uint32_t*>(g_Ql + off) = packh_res(hp, v.x, v.y);
                    } else if (seg == 1) {   // K: single (B-side of S)
                        *reinterpret_cast<uint32_t*>(g_Kk + off) = packh(v.x, v.y);
                    } else {                 // V: single (B-side of PV)
                        *reinterpret_cast<uint32_t*>(g_Vv + off) = packh(v.x, v.y);
                    }
                }
            }
        }
    }
}

// ---------------------------------------------------------------------------
// Flash attention, fp16 asymmetric split: Q split / K single, P split / V single.
// K,V [s][d] smem (pitch 136); V fragments via ldmatrix.trans; pipelined loads.
// ---------------------------------------------------------------------------
#define KSTR 136
#define SM_K 0
#define SM_V (64 * KSTR)
#define FLASH_SMEM (2 * 64 * KSTR * 2)    // 34816 B

__global__ __launch_bounds__(128, 2) void flash_mma()
{
    const int h  = blockIdx.y;
    const int qt = (gridDim.x - 1) - blockIdx.x;
    const int q0 = qt * 64;

    extern __shared__ __align__(16) __half fsm[];
    const uint32_t sbase = smem_to_u32(fsm);

    const int tid = threadIdx.x;
    const int w = tid >> 5, lane = tid & 31;
    const int r = lane >> 2, c2 = (lane & 3) * 2;
    const int brow = ((lane >> 4) & 1) * 8 + (lane & 7);
    const int bcol = ((lane >> 3) & 1) * 8;
    const int trow = lane & 15;
    const int tcol = ((lane >> 4) & 1) * 8;
    const int qrow = q0 + w * 16 + r;

    const __half* Qhg = g_Qh + (size_t)h * S_LEN * HS;
    const __half* Qlg = g_Ql + (size_t)h * S_LEN * HS;
    const __half* Kg  = g_Kk + (size_t)h * S_LEN * HS;
    const __half* Vg  = g_Vv + (size_t)h * S_LEN * HS;

    auto load_K = [&](int kt) {
        const int kb0 = kt * 64;
#pragma unroll
        for (int i = 0; i < 8; i++) {
            int c = i * 128 + tid;
            int row = c >> 4, col = c & 15;
            cp_async16(sbase + SM_K * 2 + (uint32_t)(row * KSTR + col * 8) * 2,
                       Kg + (size_t)(kb0 + row) * HS + col * 8);
        }
    };
    auto load_V = [&](int kt) {
        const int kb0 = kt * 64;
#pragma unroll
        for (int i = 0; i < 8; i++) {
            int c = i * 128 + tid;
            int row = c >> 4, col = c & 15;
            cp_async16(sbase + SM_V * 2 + (uint32_t)(row * KSTR + col * 8) * 2,
                       Vg + (size_t)(kb0 + row) * HS + col * 8);
        }
    };

    // preload Q fragments (registers)
    uint32_t qh[8][4], ql[8][4];
#pragma unroll
    for (int kc = 0; kc < 8; kc++) {
        size_t o0 = (size_t)qrow * HS + kc * 16 + c2;
        size_t o1 = (size_t)(qrow + 8) * HS + kc * 16 + c2;
        qh[kc][0] = *reinterpret_cast<const uint32_t*>(Qhg + o0);
        qh[kc][1] = *reinterpret_cast<const uint32_t*>(Qhg + o1);
        qh[kc][2] = *reinterpret_cast<const uint32_t*>(Qhg + o0 + 8);
        qh[kc][3] = *reinterpret_cast<const uint32_t*>(Qhg + o1 + 8);
        ql[kc][0] = *reinterpret_cast<const uint32_t*>(Qlg + o0);
        ql[kc][1] = *reinterpret_cast<const uint32_t*>(Qlg + o1);
        ql[kc][2] = *reinterpret_cast<const uint32_t*>(Qlg + o0 + 8);
        ql[kc][3] = *reinterpret_cast<const uint32_t*>(Qlg + o1 + 8);
    }

    load_K(0); CP_COMMIT();
    load_V(0); CP_COMMIT();

    float o[16][4];
#pragma unroll
    for (int t = 0; t < 16; t++)
#pragma unroll
        for (int q = 0; q < 4; q++) o[t][q] = 0.f;
    float m2[2] = {-1e30f, -1e30f};
    float l[2] = {0.f, 0.f};

    const float SC = INV_NORM * 1.4426950408889634f;

    for (int kt = 0; kt <= qt; kt++) {
        const int kb0 = kt * 64;
        CP_WAIT(1);              // K(kt) landed
        __syncthreads();

        // ---- S = Q K^T ----
        float sacc[8][4];
#pragma unroll
        for (int j = 0; j < 8; j++)
#pragma unroll
            for (int q = 0; q < 4; q++) sacc[j][q] = 0.f;
#pragma unroll
        for (int kc = 0; kc < 8; kc++) {
#pragma unroll
            for (int jh = 0; jh < 2; jh++) {
                uint32_t bh[4][2];
#pragma unroll
                for (int jp = 0; jp < 2; jp++) {
                    uint32_t a = sbase + SM_K * 2
                        + (uint32_t)(((jh * 4 + jp * 2) * 8 + brow) * KSTR
                                     + kc * 16 + bcol) * 2;
                    ldsm4(bh[jp * 2][0], bh[jp * 2][1],
                          bh[jp * 2 + 1][0], bh[jp * 2 + 1][1], a);
                }
#pragma unroll
                for (int jj = 0; jj < 4; jj++) mma_f16(sacc[jh * 4 + jj], qh[kc], bh[jj]);
#pragma unroll
                for (int jj = 0; jj < 4; jj++) mma_f16(sacc[jh * 4 + jj], ql[kc], bh[jj]);
            }
        }

        if (kt == qt) {           // causal mask, diagonal tile
#pragma unroll
            for (int j = 0; j < 8; j++) {
#pragma unroll
                for (int q = 0; q < 4; q++) {
                    int col = kb0 + j * 8 + c2 + (q & 1);
                    int row = qrow + ((q >= 2) ? 8 : 0);
                    if (col > row) sacc[j][q] = -1e30f;
                }
            }
        }

        // ---- online softmax ----
#pragma unroll
        for (int g = 0; g < 2; g++) {
            float rm = -1e30f;
#pragma unroll
            for (int j = 0; j < 8; j++)
                rm = fmaxf(rm, fmaxf(sacc[j][2 * g], sacc[j][2 * g + 1]));
            rm *= SC;
            rm = fmaxf(rm, __shfl_xor_sync(0xffffffffu, rm, 1));
            rm = fmaxf(rm, __shfl_xor_sync(0xffffffffu, rm, 2));
            float mn = fmaxf(m2[g], rm);
            float alpha = exp2f(m2[g] - mn);
            m2[g] = mn;
            float rs = 0.f;
#pragma unroll
            for (int j = 0; j < 8; j++) {
#pragma unroll
                for (int q = 2 * g; q < 2 * g + 2; q++) {
                    float p = exp2f(sacc[j][q] * SC - mn);
                    sacc[j][q] = p;
                    rs += p;
                }
            }
            rs += __shfl_xor_sync(0xffffffffu, rs, 1);
            rs += __shfl_xor_sync(0xffffffffu, rs, 2);
            l[g] = l[g] * alpha + rs;
#pragma unroll
            for (int t = 0; t < 16; t++) {
                o[t][2 * g]     *= alpha;
                o[t][2 * g + 1] *= alpha;
            }
        }

        __syncthreads();          // all warps done reading sK
        const bool more = (kt + 1 <= qt);
        if (more) { load_K(kt + 1); CP_COMMIT(); CP_WAIT(1); }
        else      { CP_WAIT(0); }
        __syncthreads();          // V(kt) visible

        // ---- O += P V  (P split fp16, V single via ldmatrix.trans) ----
#pragma unroll
        for (int kc2 = 0; kc2 < 4; kc2++) {
            uint32_t ph[4], pl[4];
            ph[0] = packh(sacc[2 * kc2][0], sacc[2 * kc2][1]);
            ph[1] = packh(sacc[2 * kc2][2], sacc[2 * kc2][3]);
            ph[2] = packh(sacc[2 * kc2 + 1][0], sacc[2 * kc2 + 1][1]);
            ph[3] = packh(sacc[2 * kc2 + 1][2], sacc[2 * kc2 + 1][3]);
            pl[0] = packh_res(ph[0], sacc[2 * kc2][0], sacc[2 * kc2][1]);
            pl[1] = packh_res(ph[1], sacc[2 * kc2][2], sacc[2 * kc2][3]);
            pl[2] = packh_res(ph[2], sacc[2 * kc2 + 1][0], sacc[2 * kc2 + 1][1]);
            pl[3] = packh_res(ph[3], sacc[2 * kc2 + 1][2], sacc[2 * kc2 + 1][3]);
#pragma unroll
            for (int jg = 0; jg < 8; jg++) {
                uint32_t a = sbase + SM_V * 2
                    + (uint32_t)((kc2 * 16 + trow) * KSTR + jg * 16 + tcol) * 2;
                uint32_t vh[2][2];
                ldsm4t(vh[0][0], vh[0][1], vh[1][0], vh[1][1], a);
#pragma unroll
                for (int jj = 0; jj < 2; jj++) mma_f16(o[jg * 2 + jj], ph, vh[jj]);
#pragma unroll
                for (int jj = 0; jj < 2; jj++) mma_f16(o[jg * 2 + jj], pl, vh[jj]);
            }
        }

        if (more) {
            __syncthreads();      // all warps done reading sV
            load_V(kt + 1); CP_COMMIT();
        }
    }

    float inv0 = 1.f / l[0], inv1 = 1.f / l[1];
#pragma unroll
    for (int jd = 0; jd < 16; jd++) {
        int col = h * HS + jd * 8 + c2;
        {
            float v0 = o[jd][0] * inv0, v1 = o[jd][1] * inv0;
            uint32_t hp = packh(v0, v1);
            *reinterpret_cast<uint32_t*>(g_ATh + (size_t)qrow * HID + col) = hp;
            *reinterpret_cast<uint32_t*>(g_ATl + (size_t)qrow * HID + col) =
                packh_res(hp, v0, v1);
        }
        {
            float v0 = o[jd][2] * inv1, v1 = o[jd][3] * inv1;
            uint32_t hp = packh(v0, v1);
            *reinterpret_cast<uint32_t*>(g_ATh + (size_t)(qrow + 8) * HID + col) = hp;
            *reinterpret_cast<uint32_t*>(g_ATl + (size_t)(qrow + 8) * HID + col) =
                packh_res(hp, v0, v1);
        }
    }
}

// ---------------------------------------------------------------------------
extern "C" void kernel_launch(void* const* d_in, const int* in_sizes, int n_in,
                              void* d_out, int out_size)
{
    (void)in_sizes; (void)n_in; (void)out_size;
    const float* hidden = (const float*)d_in[0];
    const float* qkvk = (const float*)d_in[2];
    const float* qkvb = (const float*)d_in[3];
    const float* outk = (const float*)d_in[4];
    const float* outb = (const float*)d_in[5];
    float* out = (float*)d_out;

    cudaFuncSetAttribute(gemm_mma, cudaFuncAttributeMaxDynamicSharedMemorySize, GEMM_SMEM);
    cudaFuncSetAttribute(flash_mma, cudaFuncAttributeMaxDynamicSharedMemorySize, FLASH_SMEM);

    void *Ah, *Al, *Bq, *Bo, *ATh, *ATl;
    cudaGetSymbolAddress(&Ah, g_Ah);   cudaGetSymbolAddress(&Al, g_Al);
    cudaGetSymbolAddress(&Bq, g_Bq);   cudaGetSymbolAddress(&Bo, g_Bo);
    cudaGetSymbolAddress(&ATh, g_ATh); cudaGetSymbolAddress(&ATl, g_ATl);

    conv_split<<<(S_LEN * HID) / 1024, 256>>>(
        (const float4*)hidden, (__half2*)Ah, (__half2*)Al);
    conv_transpose_h<<<dim3(QKV_N / 32, HID / 32), 256>>>(
        qkvk, (__half*)Bq, HID, QKV_N);
    conv_transpose_h<<<dim3(HID / 32, HID / 32), 256>>>(
        outk, (__half*)Bo, HID, HID);

    // QKV projection + fused rotary; Q split / K single / V single
    gemm_mma<<<dim3(QKV_N / 128, S_LEN / 64), 128, GEMM_SMEM>>>(
        (const __half*)Ah, (const __half*)Al, (const __half*)Bq,
        qkvb, QKV_N, nullptr, 0);

    // causal flash attention
    flash_mma<<<dim3(S_LEN / 64, NHEADS), 128, FLASH_SMEM>>>();

    // output projection
    gemm_mma<<<dim3(HID / 128, S_LEN / 64), 128, GEMM_SMEM>>>(
        (const __half*)ATh, (const __half*)ATl, (const __half*)Bo,
        outb, HID, out, 1);
}

// round 12
// speedup vs baseline: 2.0605x; 1.3556x over previous
#include <cuda_runtime.h>
#include <cuda_fp16.h>
#include <math.h>
#include <stdint.h>

#define S_LEN  2048
#define HID    2048
#define NHEADS 16
#define HS     128
#define QKV_N  6144
#define KTOT   2048
#define INV_NORM 0.08838834764831845f

// ---------------- scratch (device globals; no allocations allowed) ----------
__device__ __half g_A[(size_t)S_LEN * HID];       // hidden fp16 [m][k]
__device__ __half g_Bq[(size_t)QKV_N * HID];      // qkv kernel^T fp16 [n][k]
__device__ __half g_Bo[(size_t)HID * HID];        // out kernel^T fp16 [n][k]
__device__ __half g_AT[(size_t)S_LEN * HID];      // attn out fp16 [m][k]
__device__ __half g_Qq[(size_t)NHEADS * S_LEN * HS];   // Q fp16 [h][s][d]
__device__ __half g_Kk[(size_t)NHEADS * S_LEN * HS];   // K fp16
__device__ __half g_Vv[(size_t)NHEADS * S_LEN * HS];   // V fp16 [h][s][d]

// exact fp32 roundings of 10000^(-j/16) = 10^(-j/4)
__device__ __constant__ float c_invfreq[16] = {
    1.0f, 0.5623413251903491f, 0.31622776601683794f, 0.17782794100389228f,
    0.1f, 0.05623413251903491f, 0.03162277660168379f, 0.017782794100389228f,
    0.01f, 0.005623413251903491f, 0.0031622776601683794f, 0.0017782794100389228f,
    0.001f, 0.0005623413251903491f, 0.00031622776601683794f, 0.00017782794100389228f
};

// ------------------------------- helpers ------------------------------------
__device__ __forceinline__ uint32_t smem_to_u32(const void* p) {
    uint32_t a;
    asm("{ .reg .u64 t; cvta.to.shared.u64 t, %1; cvt.u32.u64 %0, t; }"
        : "=r"(a) : "l"(p));
    return a;
}
__device__ __forceinline__ void cp_async16(uint32_t dst, const void* src) {
    asm volatile("cp.async.cg.shared.global [%0], [%1], 16;"
                 :: "r"(dst), "l"(src) : "memory");
}
#define CP_COMMIT() asm volatile("cp.async.commit_group;" ::: "memory")
#define CP_WAIT(n)  asm volatile("cp.async.wait_group %0;" :: "n"(n) : "memory")

__device__ __forceinline__ void mma_f16(float* c, const uint32_t* a, const uint32_t* b) {
    asm volatile(
        "mma.sync.aligned.m16n8k16.row.col.f32.f16.f16.f32 "
        "{%0,%1,%2,%3}, {%4,%5,%6,%7}, {%8,%9}, {%0,%1,%2,%3};"
        : "+f"(c[0]), "+f"(c[1]), "+f"(c[2]), "+f"(c[3])
        : "r"(a[0]), "r"(a[1]), "r"(a[2]), "r"(a[3]), "r"(b[0]), "r"(b[1]));
}
__device__ __forceinline__ void ldsm4(uint32_t& r0, uint32_t& r1, uint32_t& r2,
                                      uint32_t& r3, uint32_t addr) {
    asm volatile("ldmatrix.sync.aligned.m8n8.x4.shared.b16 {%0,%1,%2,%3}, [%4];"
        : "=r"(r0), "=r"(r1), "=r"(r2), "=r"(r3) : "r"(addr));
}
__device__ __forceinline__ void ldsm4t(uint32_t& r0, uint32_t& r1, uint32_t& r2,
                                       uint32_t& r3, uint32_t addr) {
    asm volatile("ldmatrix.sync.aligned.m8n8.x4.trans.shared.b16 {%0,%1,%2,%3}, [%4];"
        : "=r"(r0), "=r"(r1), "=r"(r2), "=r"(r3) : "r"(addr));
}
// pack two fp32 -> f16x2 (lo = first element, matching mma b32 layout)
__device__ __forceinline__ uint32_t packh(float lo, float hi) {
    uint32_t d;
    asm("cvt.rn.f16x2.f32 %0, %1, %2;" : "=r"(d) : "f"(hi), "f"(lo));
    return d;
}

// ---------------------------------------------------------------------------
// Conversion kernels
// ---------------------------------------------------------------------------
__global__ __launch_bounds__(256) void conv_h(
    const float4* __restrict__ X, __half2* __restrict__ H)
{
    int i = blockIdx.x * 256 + threadIdx.x;
    float4 v = X[i];
    H[2 * i]     = __halves2half2(__float2half_rn(v.x), __float2half_rn(v.y));
    H[2 * i + 1] = __halves2half2(__float2half_rn(v.z), __float2half_rn(v.w));
}

__global__ __launch_bounds__(256) void conv_transpose_h(
    const float* __restrict__ B, __half* __restrict__ H, int K, int N)
{
    __shared__ float t[32][33];
    int x = threadIdx.x & 31, y = threadIdx.x >> 5;
    int n0 = blockIdx.x * 32, k0 = blockIdx.y * 32;
#pragma unroll
    for (int j = 0; j < 32; j += 8)
        t[y + j][x] = B[(size_t)(k0 + y + j) * N + n0 + x];
    __syncthreads();
#pragma unroll
    for (int j = 0; j < 32; j += 8)
        H[(size_t)(n0 + y + j) * K + k0 + x] = __float2half_rn(t[x][y + j]);
}

// ---------------------------------------------------------------------------
// fp16 mma.sync GEMM: C = A*B^T + bias, 1 MMA per k-step.
// BM=64, BN=128, BK=32, 128 threads, 3-stage pipeline, 3 CTAs/SM.
// mode 0 epilogue: fused rotary + Q/K/V fp16 stores.
// ---------------------------------------------------------------------------
#define GBK 32
#define GNITER (KTOT / GBK)
#define ROWSTR 40
#define A_BUFH (64 * ROWSTR)       // 2560 halves
#define B_BUFH (128 * ROWSTR)      // 5120 halves
#define ST_A 0
#define ST_B A_BUFH
#define STGH  (A_BUFH + B_BUFH)    // 7680 halves = 15360 B
#define GSTAGES 3
#define GEMM_SMEM (GSTAGES * STGH * 2)    // 46080 B

__global__ __launch_bounds__(128, 3) void gemm_mma(
    const __half* __restrict__ A, const __half* __restrict__ Bw,
    const float* __restrict__ bias, int N, float* __restrict__ Cout, int mode)
{
    extern __shared__ __align__(16) __half sm[];
    const int tid = threadIdx.x;
    const int wn = tid >> 5, lane = tid & 31;
    const int n0 = blockIdx.x * 128, m0 = blockIdx.y * 64;
    const uint32_t sbase = smem_to_u32(sm);

    const int r  = lane >> 2;
    const int c2 = (lane & 3) * 2;
    const int arow = ((lane >> 3) & 1) * 8 + (lane & 7);
    const int acol = (lane >> 4) * 8;
    const int brow = ((lane >> 4) & 1) * 8 + (lane & 7);
    const int bcol = ((lane >> 3) & 1) * 8;

    float acc[4][4][4];
#pragma unroll
    for (int i = 0; i < 4; i++)
#pragma unroll
        for (int j = 0; j < 4; j++)
#pragma unroll
            for (int q = 0; q < 4; q++) acc[i][j][q] = 0.f;

    auto load_stage = [&](int s, int k0) {
        const uint32_t st = sbase + (uint32_t)s * STGH * 2;
#pragma unroll
        for (int i = 0; i < 2; i++) {               // A: 256 chunks
            int c = tid + i * 128;
            int row = c >> 2, kc = c & 3;
            uint32_t doff = (uint32_t)(row * ROWSTR + kc * 8) * 2;
            cp_async16(st + ST_A * 2 + doff,
                       A + (size_t)(m0 + row) * KTOT + k0 + kc * 8);
        }
#pragma unroll
        for (int i = 0; i < 4; i++) {               // B: 512 chunks
            int c = tid + i * 128;
            int row = c >> 2, kc = c & 3;
            uint32_t doff = (uint32_t)(row * ROWSTR + kc * 8) * 2;
            cp_async16(st + ST_B * 2 + doff,
                       Bw + (size_t)(n0 + row) * KTOT + k0 + kc * 8);
        }
    };

    load_stage(0, 0); CP_COMMIT();
    load_stage(1, GBK); CP_COMMIT();

    for (int it = 0; it < GNITER; it++) {
        const int s = it % GSTAGES;
        if (it < GNITER - 1) { CP_WAIT(1); } else { CP_WAIT(0); }
        __syncthreads();

        const uint32_t stg = sbase + (uint32_t)s * STGH * 2;

#pragma unroll
        for (int ks = 0; ks < 2; ks++) {
            uint32_t ah[4][4], bh[4][2];
#pragma unroll
            for (int i = 0; i < 4; i++) {
                uint32_t a = stg + ST_A * 2
                           + (uint32_t)((i * 16 + arow) * ROWSTR + ks * 16 + acol) * 2;
                ldsm4(ah[i][0], ah[i][1], ah[i][2], ah[i][3], a);
            }
#pragma unroll
            for (int jp = 0; jp < 2; jp++) {
                uint32_t b = stg + ST_B * 2
                           + (uint32_t)((wn * 32 + jp * 16 + brow) * ROWSTR
                                        + ks * 16 + bcol) * 2;
                ldsm4(bh[jp * 2][0], bh[jp * 2][1],
                      bh[jp * 2 + 1][0], bh[jp * 2 + 1][1], b);
            }
#pragma unroll
            for (int i = 0; i < 4; i++)
#pragma unroll
                for (int j = 0; j < 4; j++) mma_f16(acc[i][j], ah[i], bh[j]);
        }
        if (it + 2 < GNITER) {
            load_stage((it + 2) % GSTAGES, (it + 2) * GBK);
            CP_COMMIT();
        }
    }

#pragma unroll
    for (int i = 0; i < 4; i++) {
#pragma unroll
        for (int j = 0; j < 4; j++) {
            int n = n0 + wn * 32 + j * 8 + c2;
            float2 bv = *reinterpret_cast<const float2*>(bias + n);
#pragma unroll
            for (int half = 0; half < 2; half++) {
                int m = m0 + i * 16 + r + half * 8;
                float2 v = make_float2(acc[i][j][half * 2] + bv.x,
                                       acc[i][j][half * 2 + 1] + bv.y);
                if (mode) {
                    *reinterpret_cast<float2*>(Cout + (size_t)m * N + n) = v;
                } else {
                    int h = n / 384, e = n - h * 384;
                    int seg = e >> 7, d = e & 127;
                    if (seg < 2 && d < 32) {   // fused rotary: partner acc[i][j±2]
                        bool low = d < 16;
                        int jp = low ? j + 2 : j - 2;
                        int np = low ? n + 16 : n - 16;
                        float2 bvp = *reinterpret_cast<const float2*>(bias + np);
                        float px = acc[i][jp][half * 2] + bvp.x;
                        float py = acc[i][jp][half * 2 + 1] + bvp.y;
                        float f0 = (float)m * c_invfreq[d & 15];
                        float f1 = (float)m * c_invfreq[(d + 1) & 15];
                        float s0, c0, s1, c1;
                        sincosf(f0, &s0, &c0);
                        sincosf(f1, &s1, &c1);
                        if (low) { v.x = v.x * c0 - px * s0; v.y = v.y * c1 - py * s1; }
                        else     { v.x = v.x * c0 + px * s0; v.y = v.y * c1 + py * s1; }
                    }
                    size_t off = ((size_t)h * S_LEN + m) * HS + d;
                    uint32_t hp = packh(v.x, v.y);
                    if (seg == 0)      *reinterpret_cast<uint32_t*>(g_Qq + off) = hp;
                    else if (seg == 1) *reinterpret_cast<uint32_t*>(g_Kk + off) = hp;
                    else               *reinterpret_cast<uint32_t*>(g_Vv + off) = hp;
                }
            }
        }
    }
}

// ---------------------------------------------------------------------------
// Flash attention, plain fp16 mma.sync. K,V [s][d] smem (pitch 136);
// V fragments via ldmatrix.trans; pipelined K/V loads.
// ---------------------------------------------------------------------------
#define KSTR 136
#define SM_K 0
#define SM_V (64 * KSTR)
#define FLASH_SMEM (2 * 64 * KSTR * 2)    // 34816 B

__global__ __launch_bounds__(128, 2) void flash_mma()
{
    const int h  = blockIdx.y;
    const int qt = (gridDim.x - 1) - blockIdx.x;
    const int q0 = qt * 64;

    extern __shared__ __align__(16) __half fsm[];
    const uint32_t sbase = smem_to_u32(fsm);

    const int tid = threadIdx.x;
    const int w = tid >> 5, lane = tid & 31;
    const int r = lane >> 2, c2 = (lane & 3) * 2;
    const int brow = ((lane >> 4) & 1) * 8 + (lane & 7);
    const int bcol = ((lane >> 3) & 1) * 8;
    const int trow = lane & 15;
    const int tcol = ((lane >> 4) & 1) * 8;
    const int qrow = q0 + w * 16 + r;

    const __half* Qg = g_Qq + (size_t)h * S_LEN * HS;
    const __half* Kg = g_Kk + (size_t)h * S_LEN * HS;
    const __half* Vg = g_Vv + (size_t)h * S_LEN * HS;

    auto load_K = [&](int kt) {
        const int kb0 = kt * 64;
#pragma unroll
        for (int i = 0; i < 8; i++) {
            int c = i * 128 + tid;
            int row = c >> 4, col = c & 15;
            cp_async16(sbase + SM_K * 2 + (uint32_t)(row * KSTR + col * 8) * 2,
                       Kg + (size_t)(kb0 + row) * HS + col * 8);
        }
    };
    auto load_V = [&](int kt) {
        const int kb0 = kt * 64;
#pragma unroll
        for (int i = 0; i < 8; i++) {
            int c = i * 128 + tid;
            int row = c >> 4, col = c & 15;
            cp_async16(sbase + SM_V * 2 + (uint32_t)(row * KSTR + col * 8) * 2,
                       Vg + (size_t)(kb0 + row) * HS + col * 8);
        }
    };

    // preload Q fragments (registers)
    uint32_t qh[8][4];
#pragma unroll
    for (int kc = 0; kc < 8; kc++) {
        size_t o0 = (size_t)qrow * HS + kc * 16 + c2;
        size_t o1 = (size_t)(qrow + 8) * HS + kc * 16 + c2;
        qh[kc][0] = *reinterpret_cast<const uint32_t*>(Qg + o0);
        qh[kc][1] = *reinterpret_cast<const uint32_t*>(Qg + o1);
        qh[kc][2] = *reinterpret_cast<const uint32_t*>(Qg + o0 + 8);
        qh[kc][3] = *reinterpret_cast<const uint32_t*>(Qg + o1 + 8);
    }

    load_K(0); CP_COMMIT();
    load_V(0); CP_COMMIT();

    float o[16][4];
#pragma unroll
    for (int t = 0; t < 16; t++)
#pragma unroll
        for (int q = 0; q < 4; q++) o[t][q] = 0.f;
    float m2[2] = {-1e30f, -1e30f};
    float l[2] = {0.f, 0.f};

    const float SC = INV_NORM * 1.4426950408889634f;

    for (int kt = 0; kt <= qt; kt++) {
        const int kb0 = kt * 64;
        CP_WAIT(1);              // K(kt) landed
        __syncthreads();

        // ---- S = Q K^T ----
        float sacc[8][4];
#pragma unroll
        for (int j = 0; j < 8; j++)
#pragma unroll
            for (int q = 0; q < 4; q++) sacc[j][q] = 0.f;
#pragma unroll
        for (int kc = 0; kc < 8; kc++) {
#pragma unroll
            for (int jh = 0; jh < 2; jh++) {
                uint32_t bh[4][2];
#pragma unroll
                for (int jp = 0; jp < 2; jp++) {
                    uint32_t a = sbase + SM_K * 2
                        + (uint32_t)(((jh * 4 + jp * 2) * 8 + brow) * KSTR
                                     + kc * 16 + bcol) * 2;
                    ldsm4(bh[jp * 2][0], bh[jp * 2][1],
                          bh[jp * 2 + 1][0], bh[jp * 2 + 1][1], a);
                }
#pragma unroll
                for (int jj = 0; jj < 4; jj++) mma_f16(sacc[jh * 4 + jj], qh[kc], bh[jj]);
            }
        }

        if (kt == qt) {           // causal mask, diagonal tile
#pragma unroll
            for (int j = 0; j < 8; j++) {
#pragma unroll
                for (int q = 0; q < 4; q++) {
                    int col = kb0 + j * 8 + c2 + (q & 1);
                    int row = qrow + ((q >= 2) ? 8 : 0);
                    if (col > row) sacc[j][q] = -1e30f;
                }
            }
        }

        // ---- online softmax ----
#pragma unroll
        for (int g = 0; g < 2; g++) {
            float rm = -1e30f;
#pragma unroll
            for (int j = 0; j < 8; j++)
                rm = fmaxf(rm, fmaxf(sacc[j][2 * g], sacc[j][2 * g + 1]));
            rm *= SC;
            rm = fmaxf(rm, __shfl_xor_sync(0xffffffffu, rm, 1));
            rm = fmaxf(rm, __shfl_xor_sync(0xffffffffu, rm, 2));
            float mn = fmaxf(m2[g], rm);
            float alpha = exp2f(m2[g] - mn);
            m2[g] = mn;
            float rs = 0.f;
#pragma unroll
            for (int j = 0; j < 8; j++) {
#pragma unroll
                for (int q = 2 * g; q < 2 * g + 2; q++) {
                    float p = exp2f(sacc[j][q] * SC - mn);
                    sacc[j][q] = p;
                    rs += p;
                }
            }
            rs += __shfl_xor_sync(0xffffffffu, rs, 1);
            rs += __shfl_xor_sync(0xffffffffu, rs, 2);
            l[g] = l[g] * alpha + rs;
#pragma unroll
            for (int t = 0; t < 16; t++) {
                o[t][2 * g]     *= alpha;
                o[t][2 * g + 1] *= alpha;
            }
        }

        __syncthreads();          // all warps done reading sK
        const bool more = (kt + 1 <= qt);
        if (more) { load_K(kt + 1); CP_COMMIT(); CP_WAIT(1); }
        else      { CP_WAIT(0); }
        __syncthreads();          // V(kt) visible

        // ---- O += P V  (P fp16, V via ldmatrix.trans) ----
#pragma unroll
        for (int kc2 = 0; kc2 < 4; kc2++) {
            uint32_t ph[4];
            ph[0] = packh(sacc[2 * kc2][0], sacc[2 * kc2][1]);
            ph[1] = packh(sacc[2 * kc2][2], sacc[2 * kc2][3]);
            ph[2] = packh(sacc[2 * kc2 + 1][0], sacc[2 * kc2 + 1][1]);
            ph[3] = packh(sacc[2 * kc2 + 1][2], sacc[2 * kc2 + 1][3]);
#pragma unroll
            for (int jg = 0; jg < 8; jg++) {
                uint32_t a = sbase + SM_V * 2
                    + (uint32_t)((kc2 * 16 + trow) * KSTR + jg * 16 + tcol) * 2;
                uint32_t vh[2][2];
                ldsm4t(vh[0][0], vh[0][1], vh[1][0], vh[1][1], a);
#pragma unroll
                for (int jj = 0; jj < 2; jj++) mma_f16(o[jg * 2 + jj], ph, vh[jj]);
            }
        }

        if (more) {
            __syncthreads();      // all warps done reading sV
            load_V(kt + 1); CP_COMMIT();
        }
    }

    float inv0 = 1.f / l[0], inv1 = 1.f / l[1];
#pragma unroll
    for (int jd = 0; jd < 16; jd++) {
        int col = h * HS + jd * 8 + c2;
        *reinterpret_cast<uint32_t*>(g_AT + (size_t)qrow * HID + col) =
            packh(o[jd][0] * inv0, o[jd][1] * inv0);
        *reinterpret_cast<uint32_t*>(g_AT + (size_t)(qrow + 8) * HID + col) =
            packh(o[jd][2] * inv1, o[jd][3] * inv1);
    }
}

// ---------------------------------------------------------------------------
extern "C" void kernel_launch(void* const* d_in, const int* in_sizes, int n_in,
                              void* d_out, int out_size)
{
    (void)in_sizes; (void)n_in; (void)out_size;
    const float* hidden = (const float*)d_in[0];
    const float* qkvk = (const float*)d_in[2];
    const float* qkvb = (const float*)d_in[3];
    const float* outk = (const float*)d_in[4];
    const float* outb = (const float*)d_in[5];
    float* out = (float*)d_out;

    cudaFuncSetAttribute(gemm_mma, cudaFuncAttributeMaxDynamicSharedMemorySize, GEMM_SMEM);
    cudaFuncSetAttribute(flash_mma, cudaFuncAttributeMaxDynamicSharedMemorySize, FLASH_SMEM);

    void *A, *Bq, *Bo, *AT;
    cudaGetSymbolAddress(&A, g_A);
    cudaGetSymbolAddress(&Bq, g_Bq);   cudaGetSymbolAddress(&Bo, g_Bo);
    cudaGetSymbolAddress(&AT, g_AT);

    conv_h<<<(S_LEN * HID) / 1024, 256>>>((const float4*)hidden, (__half2*)A);
    conv_transpose_h<<<dim3(QKV_N / 32, HID / 32), 256>>>(
        qkvk, (__half*)Bq, HID, QKV_N);
    conv_transpose_h<<<dim3(HID / 32, HID / 32), 256>>>(
        outk, (__half*)Bo, HID, HID);

    // QKV projection + fused rotary; Q/K/V fp16
    gemm_mma<<<dim3(QKV_N / 128, S_LEN / 64), 128, GEMM_SMEM>>>(
        (const __half*)A, (const __half*)Bq, qkvb, QKV_N, nullptr, 0);

    // causal flash attention
    flash_mma<<<dim3(S_LEN / 64, NHEADS), 128, FLASH_SMEM>>>();

    // output projection
    gemm_mma<<<dim3(HID / 128, S_LEN / 64), 128, GEMM_SMEM>>>(
        (const __half*)AT, (const __half*)Bo, outb, HID, out, 1);
}

// round 13
// speedup vs baseline: 2.2344x; 1.0844x over previous
#include <cuda_runtime.h>
#include <cuda_fp16.h>
#include <math.h>
#include <stdint.h>

#define S_LEN  2048
#define HID    2048
#define NHEADS 16
#define HS     128
#define QKV_N  6144
#define KTOT   2048
#define INV_NORM 0.08838834764831845f

// ---------------- scratch (device globals; no allocations allowed) ----------
__device__ __half g_A[(size_t)S_LEN * HID];       // hidden fp16 [m][k]
__device__ __half g_Bq[(size_t)QKV_N * HID];      // qkv kernel^T fp16 [n][k]
__device__ __half g_Bo[(size_t)HID * HID];        // out kernel^T fp16 [n][k]
__device__ __half g_AT[(size_t)S_LEN * HID];      // attn out fp16 [m][k]
__device__ __half g_Qq[(size_t)NHEADS * S_LEN * HS];   // Q fp16 [h][s][d]
__device__ __half g_Kk[(size_t)NHEADS * S_LEN * HS];   // K fp16
__device__ __half g_Vv[(size_t)NHEADS * S_LEN * HS];   // V fp16 [h][s][d]

// exact fp32 roundings of 10000^(-j/16) = 10^(-j/4)
__device__ __constant__ float c_invfreq[16] = {
    1.0f, 0.5623413251903491f, 0.31622776601683794f, 0.17782794100389228f,
    0.1f, 0.05623413251903491f, 0.03162277660168379f, 0.017782794100389228f,
    0.01f, 0.005623413251903491f, 0.0031622776601683794f, 0.0017782794100389228f,
    0.001f, 0.0005623413251903491f, 0.00031622776601683794f, 0.00017782794100389228f
};

// ------------------------------- helpers ------------------------------------
__device__ __forceinline__ uint32_t smem_to_u32(const void* p) {
    uint32_t a;
    asm("{ .reg .u64 t; cvta.to.shared.u64 t, %1; cvt.u32.u64 %0, t; }"
        : "=r"(a) : "l"(p));
    return a;
}
__device__ __forceinline__ void cp_async16(uint32_t dst, const void* src) {
    asm volatile("cp.async.cg.shared.global [%0], [%1], 16;"
                 :: "r"(dst), "l"(src) : "memory");
}
#define CP_COMMIT() asm volatile("cp.async.commit_group;" ::: "memory")
#define CP_WAIT(n)  asm volatile("cp.async.wait_group %0;" :: "n"(n) : "memory")

__device__ __forceinline__ void mma_f16(float* c, const uint32_t* a, const uint32_t* b) {
    asm volatile(
        "mma.sync.aligned.m16n8k16.row.col.f32.f16.f16.f32 "
        "{%0,%1,%2,%3}, {%4,%5,%6,%7}, {%8,%9}, {%0,%1,%2,%3};"
        : "+f"(c[0]), "+f"(c[1]), "+f"(c[2]), "+f"(c[3])
        : "r"(a[0]), "r"(a[1]), "r"(a[2]), "r"(a[3]), "r"(b[0]), "r"(b[1]));
}
__device__ __forceinline__ void ldsm4(uint32_t& r0, uint32_t& r1, uint32_t& r2,
                                      uint32_t& r3, uint32_t addr) {
    asm volatile("ldmatrix.sync.aligned.m8n8.x4.shared.b16 {%0,%1,%2,%3}, [%4];"
        : "=r"(r0), "=r"(r1), "=r"(r2), "=r"(r3) : "r"(addr));
}
__device__ __forceinline__ void ldsm4t(uint32_t& r0, uint32_t& r1, uint32_t& r2,
                                       uint32_t& r3, uint32_t addr) {
    asm volatile("ldmatrix.sync.aligned.m8n8.x4.trans.shared.b16 {%0,%1,%2,%3}, [%4];"
        : "=r"(r0), "=r"(r1), "=r"(r2), "=r"(r3) : "r"(addr));
}
__device__ __forceinline__ uint32_t packh(float lo, float hi) {
    uint32_t d;
    asm("cvt.rn.f16x2.f32 %0, %1, %2;" : "=r"(d) : "f"(hi), "f"(lo));
    return d;
}

// ---------------------------------------------------------------------------
// Conversion kernels
// ---------------------------------------------------------------------------
__global__ __launch_bounds__(256) void conv_h(
    const float4* __restrict__ X, __half2* __restrict__ H)
{
    int i = blockIdx.x * 256 + threadIdx.x;
    float4 v = X[i];
    H[2 * i]     = __halves2half2(__float2half_rn(v.x), __float2half_rn(v.y));
    H[2 * i + 1] = __halves2half2(__float2half_rn(v.z), __float2half_rn(v.w));
}

__global__ __launch_bounds__(256) void conv_transpose_h(
    const float* __restrict__ B, __half* __restrict__ H, int K, int N)
{
    __shared__ float t[32][33];
    int x = threadIdx.x & 31, y = threadIdx.x >> 5;
    int n0 = blockIdx.x * 32, k0 = blockIdx.y * 32;
#pragma unroll
    for (int j = 0; j < 32; j += 8)
        t[y + j][x] = B[(size_t)(k0 + y + j) * N + n0 + x];
    __syncthreads();
#pragma unroll
    for (int j = 0; j < 32; j += 8)
        H[(size_t)(n0 + y + j) * K + k0 + x] = __float2half_rn(t[x][y + j]);
}

// ---------------------------------------------------------------------------
// fp16 mma.sync GEMM: C = A*B^T + bias. BM=64, BN=256, BK=32, 128 threads
// (4 warps side-by-side in N, warp tile 64x64), 3-stage pipeline, 2 CTAs/SM.
// mode 0 epilogue: fused rotary + Q/K/V fp16 stores.
// ---------------------------------------------------------------------------
#define GBK 32
#define GNITER (KTOT / GBK)
#define ROWSTR 40
#define A_BUFH (64 * ROWSTR)        // 2560 halves
#define B_BUFH (256 * ROWSTR)       // 10240 halves
#define ST_A 0
#define ST_B A_BUFH
#define STGH  (A_BUFH + B_BUFH)     // 12800 halves = 25600 B
#define GSTAGES 3
#define GEMM_SMEM (GSTAGES * STGH * 2)    // 76800 B

__global__ __launch_bounds__(128, 2) void gemm_mma(
    const __half* __restrict__ A, const __half* __restrict__ Bw,
    const float* __restrict__ bias, int N, float* __restrict__ Cout, int mode)
{
    extern __shared__ __align__(16) __half sm[];
    const int tid = threadIdx.x;
    const int wn = tid >> 5, lane = tid & 31;
    const int n0 = blockIdx.x * 256, m0 = blockIdx.y * 64;
    const uint32_t sbase = smem_to_u32(sm);

    const int r  = lane >> 2;
    const int c2 = (lane & 3) * 2;
    const int arow = ((lane >> 3) & 1) * 8 + (lane & 7);
    const int acol = (lane >> 4) * 8;
    const int brow = ((lane >> 4) & 1) * 8 + (lane & 7);
    const int bcol = ((lane >> 3) & 1) * 8;

    float acc[4][8][4];
#pragma unroll
    for (int i = 0; i < 4; i++)
#pragma unroll
        for (int j = 0; j < 8; j++)
#pragma unroll
            for (int q = 0; q < 4; q++) acc[i][j][q] = 0.f;

    auto load_stage = [&](int s, int k0) {
        const uint32_t st = sbase + (uint32_t)s * STGH * 2;
#pragma unroll
        for (int i = 0; i < 2; i++) {               // A: 256 chunks
            int c = tid + i * 128;
            int row = c >> 2, kc = c & 3;
            uint32_t doff = (uint32_t)(row * ROWSTR + kc * 8) * 2;
            cp_async16(st + ST_A * 2 + doff,
                       A + (size_t)(m0 + row) * KTOT + k0 + kc * 8);
        }
#pragma unroll
        for (int i = 0; i < 8; i++) {               // B: 1024 chunks
            int c = tid + i * 128;
            int row = c >> 2, kc = c & 3;
            uint32_t doff = (uint32_t)(row * ROWSTR + kc * 8) * 2;
            cp_async16(st + ST_B * 2 + doff,
                       Bw + (size_t)(n0 + row) * KTOT + k0 + kc * 8);
        }
    };

    load_stage(0, 0); CP_COMMIT();
    load_stage(1, GBK); CP_COMMIT();

    for (int it = 0; it < GNITER; it++) {
        const int s = it % GSTAGES;
        if (it < GNITER - 1) { CP_WAIT(1); } else { CP_WAIT(0); }
        __syncthreads();

        const uint32_t stg = sbase + (uint32_t)s * STGH * 2;

#pragma unroll
        for (int ks = 0; ks < 2; ks++) {
            uint32_t ah[4][4], bh[8][2];
#pragma unroll
            for (int i = 0; i < 4; i++) {
                uint32_t a = stg + ST_A * 2
                           + (uint32_t)((i * 16 + arow) * ROWSTR + ks * 16 + acol) * 2;
                ldsm4(ah[i][0], ah[i][1], ah[i][2], ah[i][3], a);
            }
#pragma unroll
            for (int jp = 0; jp < 4; jp++) {
                uint32_t b = stg + ST_B * 2
                           + (uint32_t)((wn * 64 + jp * 16 + brow) * ROWSTR
                                        + ks * 16 + bcol) * 2;
                ldsm4(bh[jp * 2][0], bh[jp * 2][1],
                      bh[jp * 2 + 1][0], bh[jp * 2 + 1][1], b);
            }
#pragma unroll
            for (int i = 0; i < 4; i++)
#pragma unroll
                for (int j = 0; j < 8; j++) mma_f16(acc[i][j], ah[i], bh[j]);
        }
        if (it + 2 < GNITER) {
            load_stage((it + 2) % GSTAGES, (it + 2) * GBK);
            CP_COMMIT();
        }
    }

#pragma unroll
    for (int i = 0; i < 4; i++) {
#pragma unroll
        for (int j = 0; j < 8; j++) {
            int n = n0 + wn * 64 + j * 8 + c2;
            float2 bv = *reinterpret_cast<const float2*>(bias + n);
#pragma unroll
            for (int half = 0; half < 2; half++) {
                int m = m0 + i * 16 + r + half * 8;
                float2 v = make_float2(acc[i][j][half * 2] + bv.x,
                                       acc[i][j][half * 2 + 1] + bv.y);
                if (mode) {
                    *reinterpret_cast<float2*>(Cout + (size_t)m * N + n) = v;
                } else {
                    int h = n / 384, e = n - h * 384;
                    int seg = e >> 7, d = e & 127;
                    if (seg < 2 && d < 32) {   // fused rotary: partner acc[i][j±2]
                        bool low = d < 16;
                        int jp = low ? j + 2 : j - 2;
                        int np = low ? n + 16 : n - 16;
                        float2 bvp = *reinterpret_cast<const float2*>(bias + np);
                        float px = acc[i][jp][half * 2] + bvp.x;
                        float py = acc[i][jp][half * 2 + 1] + bvp.y;
                        float f0 = (float)m * c_invfreq[d & 15];
                        float f1 = (float)m * c_invfreq[(d + 1) & 15];
                        float s0, c0, s1, c1;
                        sincosf(f0, &s0, &c0);
                        sincosf(f1, &s1, &c1);
                        if (low) { v.x = v.x * c0 - px * s0; v.y = v.y * c1 - py * s1; }
                        else     { v.x = v.x * c0 + px * s0; v.y = v.y * c1 + py * s1; }
                    }
                    size_t off = ((size_t)h * S_LEN + m) * HS + d;
                    uint32_t hp = packh(v.x, v.y);
                    if (seg == 0)      *reinterpret_cast<uint32_t*>(g_Qq + off) = hp;
                    else if (seg == 1) *reinterpret_cast<uint32_t*>(g_Kk + off) = hp;
                    else               *reinterpret_cast<uint32_t*>(g_Vv + off) = hp;
                }
            }
        }
    }
}

// ---------------------------------------------------------------------------
// Flash attention, plain fp16 mma.sync. K,V [s][d] smem (pitch 136);
// V fragments via ldmatrix.trans; pipelined K/V loads.
// ---------------------------------------------------------------------------
#define KSTR 136
#define SM_K 0
#define SM_V (64 * KSTR)
#define FLASH_SMEM (2 * 64 * KSTR * 2)    // 34816 B

__global__ __launch_bounds__(128, 2) void flash_mma()
{
    const int h  = blockIdx.y;
    const int qt = (gridDim.x - 1) - blockIdx.x;
    const int q0 = qt * 64;

    extern __shared__ __align__(16) __half fsm[];
    const uint32_t sbase = smem_to_u32(fsm);

    const int tid = threadIdx.x;
    const int w = tid >> 5, lane = tid & 31;
    const int r = lane >> 2, c2 = (lane & 3) * 2;
    const int brow = ((lane >> 4) & 1) * 8 + (lane & 7);
    const int bcol = ((lane >> 3) & 1) * 8;
    const int trow = lane & 15;
    const int tcol = ((lane >> 4) & 1) * 8;
    const int qrow = q0 + w * 16 + r;

    const __half* Qg = g_Qq + (size_t)h * S_LEN * HS;
    const __half* Kg = g_Kk + (size_t)h * S_LEN * HS;
    const __half* Vg = g_Vv + (size_t)h * S_LEN * HS;

    auto load_K = [&](int kt) {
        const int kb0 = kt * 64;
#pragma unroll
        for (int i = 0; i < 8; i++) {
            int c = i * 128 + tid;
            int row = c >> 4, col = c & 15;
            cp_async16(sbase + SM_K * 2 + (uint32_t)(row * KSTR + col * 8) * 2,
                       Kg + (size_t)(kb0 + row) * HS + col * 8);
        }
    };
    auto load_V = [&](int kt) {
        const int kb0 = kt * 64;
#pragma unroll
        for (int i = 0; i < 8; i++) {
            int c = i * 128 + tid;
            int row = c >> 4, col = c & 15;
            cp_async16(sbase + SM_V * 2 + (uint32_t)(row * KSTR + col * 8) * 2,
                       Vg + (size_t)(kb0 + row) * HS + col * 8);
        }
    };

    uint32_t qh[8][4];
#pragma unroll
    for (int kc = 0; kc < 8; kc++) {
        size_t o0 = (size_t)qrow * HS + kc * 16 + c2;
        size_t o1 = (size_t)(qrow + 8) * HS + kc * 16 + c2;
        qh[kc][0] = *reinterpret_cast<const uint32_t*>(Qg + o0);
        qh[kc][1] = *reinterpret_cast<const uint32_t*>(Qg + o1);
        qh[kc][2] = *reinterpret_cast<const uint32_t*>(Qg + o0 + 8);
        qh[kc][3] = *reinterpret_cast<const uint32_t*>(Qg + o1 + 8);
    }

    load_K(0); CP_COMMIT();
    load_V(0); CP_COMMIT();

    float o[16][4];
#pragma unroll
    for (int t = 0; t < 16; t++)
#pragma unroll
        for (int q = 0; q < 4; q++) o[t][q] = 0.f;
    float m2[2] = {-1e30f, -1e30f};
    float l[2] = {0.f, 0.f};

    const float SC = INV_NORM * 1.4426950408889634f;

    for (int kt = 0; kt <= qt; kt++) {
        const int kb0 = kt * 64;
        CP_WAIT(1);
        __syncthreads();

        float sacc[8][4];
#pragma unroll
        for (int j = 0; j < 8; j++)
#pragma unroll
            for (int q = 0; q < 4; q++) sacc[j][q] = 0.f;
#pragma unroll
        for (int kc = 0; kc < 8; kc++) {
#pragma unroll
            for (int jh = 0; jh < 2; jh++) {
                uint32_t bh[4][2];
#pragma unroll
                for (int jp = 0; jp < 2; jp++) {
                    uint32_t a = sbase + SM_K * 2
                        + (uint32_t)(((jh * 4 + jp * 2) * 8 + brow) * KSTR
                                     + kc * 16 + bcol) * 2;
                    ldsm4(bh[jp * 2][0], bh[jp * 2][1],
                          bh[jp * 2 + 1][0], bh[jp * 2 + 1][1], a);
                }
#pragma unroll
                for (int jj = 0; jj < 4; jj++) mma_f16(sacc[jh * 4 + jj], qh[kc], bh[jj]);
            }
        }

        if (kt == qt) {
#pragma unroll
            for (int j = 0; j < 8; j++) {
#pragma unroll
                for (int q = 0; q < 4; q++) {
                    int col = kb0 + j * 8 + c2 + (q & 1);
                    int row = qrow + ((q >= 2) ? 8 : 0);
                    if (col > row) sacc[j][q] = -1e30f;
                }
            }
        }

#pragma unroll
        for (int g = 0; g < 2; g++) {
            float rm = -1e30f;
#pragma unroll
            for (int j = 0; j < 8; j++)
                rm = fmaxf(rm, fmaxf(sacc[j][2 * g], sacc[j][2 * g + 1]));
            rm *= SC;
            rm = fmaxf(rm, __shfl_xor_sync(0xffffffffu, rm, 1));
            rm = fmaxf(rm, __shfl_xor_sync(0xffffffffu, rm, 2));
            float mn = fmaxf(m2[g], rm);
            float alpha = exp2f(m2[g] - mn);
            m2[g] = mn;
            float rs = 0.f;
#pragma unroll
            for (int j = 0; j < 8; j++) {
#pragma unroll
                for (int q = 2 * g; q < 2 * g + 2; q++) {
                    float p = exp2f(sacc[j][q] * SC - mn);
                    sacc[j][q] = p;
                    rs += p;
                }
            }
            rs += __shfl_xor_sync(0xffffffffu, rs, 1);
            rs += __shfl_xor_sync(0xffffffffu, rs, 2);
            l[g] = l[g] * alpha + rs;
#pragma unroll
            for (int t = 0; t < 16; t++) {
                o[t][2 * g]     *= alpha;
                o[t][2 * g + 1] *= alpha;
            }
        }

        __syncthreads();
        const bool more = (kt + 1 <= qt);
        if (more) { load_K(kt + 1); CP_COMMIT(); CP_WAIT(1); }
        else      { CP_WAIT(0); }
        __syncthreads();

#pragma unroll
        for (int kc2 = 0; kc2 < 4; kc2++) {
            uint32_t ph[4];
            ph[0] = packh(sacc[2 * kc2][0], sacc[2 * kc2][1]);
            ph[1] = packh(sacc[2 * kc2][2], sacc[2 * kc2][3]);
            ph[2] = packh(sacc[2 * kc2 + 1][0], sacc[2 * kc2 + 1][1]);
            ph[3] = packh(sacc[2 * kc2 + 1][2], sacc[2 * kc2 + 1][3]);
#pragma unroll
            for (int jg = 0; jg < 8; jg++) {
                uint32_t a = sbase + SM_V * 2
                    + (uint32_t)((kc2 * 16 + trow) * KSTR + jg * 16 + tcol) * 2;
                uint32_t vh[2][2];
                ldsm4t(vh[0][0], vh[0][1], vh[1][0], vh[1][1], a);
#pragma unroll
                for (int jj = 0; jj < 2; jj++) mma_f16(o[jg * 2 + jj], ph, vh[jj]);
            }
        }

        if (more) {
            __syncthreads();
            load_V(kt + 1); CP_COMMIT();
        }
    }

    float inv0 = 1.f / l[0], inv1 = 1.f / l[1];
#pragma unroll
    for (int jd = 0; jd < 16; jd++) {
        int col = h * HS + jd * 8 + c2;
        *reinterpret_cast<uint32_t*>(g_AT + (size_t)qrow * HID + col) =
            packh(o[jd][0] * inv0, o[jd][1] * inv0);
        *reinterpret_cast<uint32_t*>(g_AT + (size_t)(qrow + 8) * HID + col) =
            packh(o[jd][2] * inv1, o[jd][3] * inv1);
    }
}

// ---------------------------------------------------------------------------
extern "C" void kernel_launch(void* const* d_in, const int* in_sizes, int n_in,
                              void* d_out, int out_size)
{
    (void)in_sizes; (void)n_in; (void)out_size;
    const float* hidden = (const float*)d_in[0];
    const float* qkvk = (const float*)d_in[2];
    const float* qkvb = (const float*)d_in[3];
    const float* outk = (const float*)d_in[4];
    const float* outb = (const float*)d_in[5];
    float* out = (float*)d_out;

    cudaFuncSetAttribute(gemm_mma, cudaFuncAttributeMaxDynamicSharedMemorySize, GEMM_SMEM);
    cudaFuncSetAttribute(flash_mma, cudaFuncAttributeMaxDynamicSharedMemorySize, FLASH_SMEM);

    void *A, *Bq, *Bo, *AT;
    cudaGetSymbolAddress(&A, g_A);
    cudaGetSymbolAddress(&Bq, g_Bq);   cudaGetSymbolAddress(&Bo, g_Bo);
    cudaGetSymbolAddress(&AT, g_AT);

    conv_h<<<(S_LEN * HID) / 1024, 256>>>((const float4*)hidden, (__half2*)A);
    conv_transpose_h<<<dim3(QKV_N / 32, HID / 32), 256>>>(
        qkvk, (__half*)Bq, HID, QKV_N);
    conv_transpose_h<<<dim3(HID / 32, HID / 32), 256>>>(
        outk, (__half*)Bo, HID, HID);

    // QKV projection + fused rotary; Q/K/V fp16
    gemm_mma<<<dim3(QKV_N / 256, S_LEN / 64), 128, GEMM_SMEM>>>(
        (const __half*)A, (const __half*)Bq, qkvb, QKV_N, nullptr, 0);

    // causal flash attention
    flash_mma<<<dim3(S_LEN / 64, NHEADS), 128, FLASH_SMEM>>>();

    // output projection
    gemm_mma<<<dim3(HID / 256, S_LEN / 64), 128, GEMM_SMEM>>>(
        (const __half*)AT, (const __half*)Bo, outb, HID, out, 1);
}